// round 4
// baseline (speedup 1.0000x reference)
#include <cuda_runtime.h>
#include <math.h>

#define BATCH 8
#define SEQ   2048
#define CDIM  1024
#define HS    64
#define M_TOTAL (BATCH * SEQ)   // 16384

#define NQT    (SEQ / 64)       // 32 query tiles per batch
#define NCHUNK 8                // 8 KV chunks of 256 keys (4 tiles of 64)

// Scratch (device globals: allowed).
__device__ float g_q[M_TOTAL * HS];
__device__ float g_k[M_TOTAL * HS];
__device__ float g_v[M_TOTAL * HS];
// Split-KV partials: [B][NQT][NCHUNK][64 rows][64 cols] + per-row m,l
__device__ float g_po[(size_t)BATCH * NQT * NCHUNK * 64 * 64];
__device__ float g_pm[BATCH * NQT * NCHUNK * 64];
__device__ float g_pl[BATCH * NQT * NCHUNK * 64];

// ---------------------------------------------------------------------------
// packed f32x2 helpers (sm_100+): FFMA2 = 2 fp32 FMAs per issue slot.
// ---------------------------------------------------------------------------
__device__ __forceinline__ void ffma2(unsigned long long& d,
                                      unsigned long long a,
                                      unsigned long long b) {
    asm("fma.rn.f32x2 %0, %1, %2, %0;" : "+l"(d) : "l"(a), "l"(b));
}
__device__ __forceinline__ float2 unpack2(unsigned long long v) {
    float2 r;
    asm("mov.b64 {%0, %1}, %2;" : "=f"(r.x), "=f"(r.y) : "l"(v));
    return r;
}

// ---------------------------------------------------------------------------
// Kernel 1: QKV projection. [M_TOTAL,CDIM] x [CDIM,HS] -> [M_TOTAL,HS]
// grid = (128, 3), block = 128. 128x64 tile, BK=16, thread tile 8x8,
// computed as 4 row-pairs x 8 cols of packed f32x2 FMAs.
//   A smem transposed  -> row-pairs load naturally via LDS.64
//   B smem duplicated  -> column-broadcast pairs load naturally via LDS.128
// ---------------------------------------------------------------------------
#define QKV_BM 128
#define QKV_BK 16

__global__ __launch_bounds__(128) void qkv_kernel(
    const float* __restrict__ xq, const float* __restrict__ xkv,
    const float* __restrict__ Wq, const float* __restrict__ Wk,
    const float* __restrict__ Wv)
{
    const int which = blockIdx.y;                 // 0=Q, 1=K, 2=V
    const float* __restrict__ X = (which == 0) ? xq : xkv;
    const float* __restrict__ W = (which == 0) ? Wq : (which == 1 ? Wk : Wv);
    float* __restrict__ O = (which == 0) ? g_q : (which == 1 ? g_k : g_v);

    __shared__ __align__(16) float As[QKV_BK][132];   // [k][m], padded
    __shared__ __align__(16) float Bsd[QKV_BK][128];  // dup layout, see below

    const int tid  = threadIdx.x;
    const int trow = tid >> 3;             // 0..15 -> rows trow*8 .. +7
    const int tcol = tid & 7;              // 0..7  -> cols tcol*8 .. +7
    const int m0   = blockIdx.x * QKV_BM;

    unsigned long long acc2[4][8];         // [row-pair][col]; lo=row 2rp, hi=row 2rp+1
#pragma unroll
    for (int rp = 0; rp < 4; rp++)
#pragma unroll
        for (int c = 0; c < 8; c++) acc2[rp][c] = 0ull;

    for (int k0 = 0; k0 < CDIM; k0 += QKV_BK) {
        // A tile: 128x16 = 512 float4, 4 per thread, stored transposed.
#pragma unroll
        for (int i = 0; i < 4; i++) {
            int idx = tid + i * 128;       // 0..511
            int r   = idx >> 2;
            int c4  = (idx & 3) * 4;
            const float4 v = *(const float4*)&X[(size_t)(m0 + r) * CDIM + k0 + c4];
            As[c4 + 0][r] = v.x;
            As[c4 + 1][r] = v.y;
            As[c4 + 2][r] = v.z;
            As[c4 + 3][r] = v.w;
        }
        // B tile: 16x64 = 256 float4, 2 per thread; store duplicated:
        // chunk (cc*8 + tc) at Bsd[r][chunk*4] = {B[col],B[col],B[col+1],B[col+1]}
        // with col = tc*8 + 2*cc.
#pragma unroll
        for (int i = 0; i < 2; i++) {
            int idx = tid + i * 128;       // 0..255
            int r   = idx >> 4;
            int c4  = (idx & 15) * 4;
            const float4 w = *(const float4*)&W[(size_t)(k0 + r) * HS + c4];
            int tc = c4 >> 3;
            int cc = (c4 & 7) >> 1;        // 0 or 2
            *(float4*)&Bsd[r][(cc * 8 + tc) * 4]       = make_float4(w.x, w.x, w.y, w.y);
            *(float4*)&Bsd[r][((cc + 1) * 8 + tc) * 4] = make_float4(w.z, w.z, w.w, w.w);
        }
        __syncthreads();

#pragma unroll
        for (int k = 0; k < QKV_BK; k++) {
            unsigned long long a2[4];
#pragma unroll
            for (int rp = 0; rp < 4; rp++)
                a2[rp] = *(const unsigned long long*)&As[k][trow * 8 + 2 * rp];
            ulonglong2 b[4];
#pragma unroll
            for (int cc = 0; cc < 4; cc++)
                b[cc] = *(const ulonglong2*)&Bsd[k][(cc * 8 + tcol) * 4];
#pragma unroll
            for (int rp = 0; rp < 4; rp++)
#pragma unroll
                for (int cc = 0; cc < 4; cc++) {
                    ffma2(acc2[rp][2 * cc],     a2[rp], b[cc].x);
                    ffma2(acc2[rp][2 * cc + 1], a2[rp], b[cc].y);
                }
        }
        __syncthreads();
    }

    // Store: unpack pairs -> two rows of 8 floats per rp.
#pragma unroll
    for (int rp = 0; rp < 4; rp++) {
        float lo[8], hi[8];
#pragma unroll
        for (int c = 0; c < 8; c++) {
            float2 u = unpack2(acc2[rp][c]);
            lo[c] = u.x; hi[c] = u.y;
        }
        size_t r0 = (size_t)(m0 + trow * 8 + 2 * rp) * HS + tcol * 8;
        *(float4*)&O[r0]          = make_float4(lo[0], lo[1], lo[2], lo[3]);
        *(float4*)&O[r0 + 4]      = make_float4(lo[4], lo[5], lo[6], lo[7]);
        *(float4*)&O[r0 + HS]     = make_float4(hi[0], hi[1], hi[2], hi[3]);
        *(float4*)&O[r0 + HS + 4] = make_float4(hi[4], hi[5], hi[6], hi[7]);
    }
}

// ---------------------------------------------------------------------------
// Kernel 2: split-KV causal flash attention (partials).
// grid = (NQT, NCHUNK, BATCH), block = 256. Each CTA: one 64-row Q tile x
// one 256-key chunk (<=4 KV tiles). Writes unnormalized o + (m, l).
// ---------------------------------------------------------------------------
__global__ __launch_bounds__(256) void attn_partial(void)
{
    const int qt  = blockIdx.x;            // 0..31
    const int cix = blockIdx.y;            // 0..7
    const int bb  = blockIdx.z;            // 0..7
    if (cix * 4 > qt) return;              // chunk entirely above diagonal

    __shared__ float Qs[64][64];    // Qs[i][h]
    __shared__ float KVs[64][64];   // first K^T: KVs[h][j]; then V: KVs[k][j]
    __shared__ float Ps[64][64];    // P[i][j]

    const int tid = threadIdx.x;
    const int tx  = tid & 15;
    const int ty  = tid >> 4;
    const int i0  = ty * 4;
    const int j0  = tx * 4;

    const float scale = 0.03125f;          // 1024^-0.5

    const float* Qg = g_q + ((size_t)bb * SEQ + qt * 64) * HS;
#pragma unroll
    for (int i = 0; i < 4; i++) {
        int idx = tid + i * 256;
        int r   = idx >> 4;
        int c4  = (idx & 15) * 4;
        *(float4*)&Qs[r][c4] = *(const float4*)&Qg[r * HS + c4];
    }

    float o[4][4];
    float m_run[4], l_run[4];
#pragma unroll
    for (int r = 0; r < 4; r++) {
        m_run[r] = -INFINITY;
        l_run[r] = 0.f;
#pragma unroll
        for (int c = 0; c < 4; c++) o[r][c] = 0.f;
    }

    const int kt_begin = cix * 4;
    const int kt_end   = (cix * 4 + 3 < qt) ? (cix * 4 + 3) : qt;

    for (int kt = kt_begin; kt <= kt_end; kt++) {
        const float* Kg = g_k + ((size_t)bb * SEQ + kt * 64) * HS;
        const float* Vg = g_v + ((size_t)bb * SEQ + kt * 64) * HS;

        // K tile transposed: KVs[h][j].
#pragma unroll
        for (int i = 0; i < 4; i++) {
            int idx = tid + i * 256;
            int r   = idx >> 4;
            int c4  = (idx & 15) * 4;
            float4 v = *(const float4*)&Kg[r * HS + c4];
            KVs[c4 + 0][r] = v.x;
            KVs[c4 + 1][r] = v.y;
            KVs[c4 + 2][r] = v.z;
            KVs[c4 + 3][r] = v.w;
        }
        __syncthreads();

        float s[4][4];
#pragma unroll
        for (int r = 0; r < 4; r++)
#pragma unroll
            for (int c = 0; c < 4; c++) s[r][c] = 0.f;

        for (int h = 0; h < 64; h++) {
            float4 bv = *(const float4*)&KVs[h][j0];
            float a0 = Qs[i0 + 0][h];
            float a1 = Qs[i0 + 1][h];
            float a2 = Qs[i0 + 2][h];
            float a3 = Qs[i0 + 3][h];
            s[0][0] = fmaf(a0, bv.x, s[0][0]); s[0][1] = fmaf(a0, bv.y, s[0][1]);
            s[0][2] = fmaf(a0, bv.z, s[0][2]); s[0][3] = fmaf(a0, bv.w, s[0][3]);
            s[1][0] = fmaf(a1, bv.x, s[1][0]); s[1][1] = fmaf(a1, bv.y, s[1][1]);
            s[1][2] = fmaf(a1, bv.z, s[1][2]); s[1][3] = fmaf(a1, bv.w, s[1][3]);
            s[2][0] = fmaf(a2, bv.x, s[2][0]); s[2][1] = fmaf(a2, bv.y, s[2][1]);
            s[2][2] = fmaf(a2, bv.z, s[2][2]); s[2][3] = fmaf(a2, bv.w, s[2][3]);
            s[3][0] = fmaf(a3, bv.x, s[3][0]); s[3][1] = fmaf(a3, bv.y, s[3][1]);
            s[3][2] = fmaf(a3, bv.z, s[3][2]); s[3][3] = fmaf(a3, bv.w, s[3][3]);
        }

        const bool diag = (kt == qt);
#pragma unroll
        for (int r = 0; r < 4; r++)
#pragma unroll
            for (int c = 0; c < 4; c++) {
                float sv = s[r][c] * scale;
                if (diag && (j0 + c) > (i0 + r)) sv = -INFINITY;
                s[r][c] = sv;
            }

        float rmax[4];
#pragma unroll
        for (int r = 0; r < 4; r++)
            rmax[r] = fmaxf(fmaxf(s[r][0], s[r][1]), fmaxf(s[r][2], s[r][3]));
#pragma unroll
        for (int off = 8; off > 0; off >>= 1)
#pragma unroll
            for (int r = 0; r < 4; r++)
                rmax[r] = fmaxf(rmax[r], __shfl_xor_sync(0xffffffffu, rmax[r], off));

        float alpha[4];
#pragma unroll
        for (int r = 0; r < 4; r++) {
            float mn = fmaxf(m_run[r], rmax[r]);
            alpha[r] = __expf(m_run[r] - mn);
            m_run[r] = mn;
        }

        float rsum[4] = {0.f, 0.f, 0.f, 0.f};
#pragma unroll
        for (int r = 0; r < 4; r++)
#pragma unroll
            for (int c = 0; c < 4; c++) {
                float p = __expf(s[r][c] - m_run[r]);
                Ps[i0 + r][j0 + c] = p;
                rsum[r] += p;
            }
#pragma unroll
        for (int off = 8; off > 0; off >>= 1)
#pragma unroll
            for (int r = 0; r < 4; r++)
                rsum[r] += __shfl_xor_sync(0xffffffffu, rsum[r], off);

#pragma unroll
        for (int r = 0; r < 4; r++) {
            l_run[r] = l_run[r] * alpha[r] + rsum[r];
#pragma unroll
            for (int c = 0; c < 4; c++) o[r][c] *= alpha[r];
        }

        __syncthreads();

        // V tile: KVs[k][j].
#pragma unroll
        for (int i = 0; i < 4; i++) {
            int idx = tid + i * 256;
            int r   = idx >> 4;
            int c4  = (idx & 15) * 4;
            *(float4*)&KVs[r][c4] = *(const float4*)&Vg[r * HS + c4];
        }
        __syncthreads();

        for (int k = 0; k < 64; k++) {
            float4 bv = *(const float4*)&KVs[k][j0];
            float p0 = Ps[i0 + 0][k];
            float p1 = Ps[i0 + 1][k];
            float p2 = Ps[i0 + 2][k];
            float p3 = Ps[i0 + 3][k];
            o[0][0] = fmaf(p0, bv.x, o[0][0]); o[0][1] = fmaf(p0, bv.y, o[0][1]);
            o[0][2] = fmaf(p0, bv.z, o[0][2]); o[0][3] = fmaf(p0, bv.w, o[0][3]);
            o[1][0] = fmaf(p1, bv.x, o[1][0]); o[1][1] = fmaf(p1, bv.y, o[1][1]);
            o[1][2] = fmaf(p1, bv.z, o[1][2]); o[1][3] = fmaf(p1, bv.w, o[1][3]);
            o[2][0] = fmaf(p2, bv.x, o[2][0]); o[2][1] = fmaf(p2, bv.y, o[2][1]);
            o[2][2] = fmaf(p2, bv.z, o[2][2]); o[2][3] = fmaf(p2, bv.w, o[2][3]);
            o[3][0] = fmaf(p3, bv.x, o[3][0]); o[3][1] = fmaf(p3, bv.y, o[3][1]);
            o[3][2] = fmaf(p3, bv.z, o[3][2]); o[3][3] = fmaf(p3, bv.w, o[3][3]);
        }
        __syncthreads();
    }

    // Store partials (unnormalized o, plus m, l).
    const size_t p = ((size_t)(bb * NQT + qt) * NCHUNK + cix);
#pragma unroll
    for (int r = 0; r < 4; r++) {
        *(float4*)&g_po[p * 4096 + (i0 + r) * 64 + j0] =
            make_float4(o[r][0], o[r][1], o[r][2], o[r][3]);
    }
    if (tx == 0) {
#pragma unroll
        for (int r = 0; r < 4; r++) {
            g_pm[p * 64 + i0 + r] = m_run[r];
            g_pl[p * 64 + i0 + r] = l_run[r];
        }
    }
}

// ---------------------------------------------------------------------------
// Kernel 3: combine split-KV partials. grid = (NQT, BATCH), block = 256.
// ---------------------------------------------------------------------------
__global__ __launch_bounds__(256) void attn_reduce(float* __restrict__ out)
{
    const int qt = blockIdx.x;
    const int bb = blockIdx.y;
    const int nc = qt / 4 + 1;             // chunks touching this q tile

    __shared__ float w[NCHUNK][64];
    __shared__ float invL[64];

    const int tid = threadIdx.x;
    const size_t pbase = (size_t)(bb * NQT + qt) * NCHUNK;

    if (tid < 64) {
        const int row = tid;
        float M = -INFINITY;
        for (int c = 0; c < nc; c++)
            M = fmaxf(M, g_pm[(pbase + c) * 64 + row]);
        float L = 0.f;
        for (int c = 0; c < nc; c++) {
            float wi = __expf(g_pm[(pbase + c) * 64 + row] - M);
            w[c][row] = wi;
            L += wi * g_pl[(pbase + c) * 64 + row];
        }
        invL[row] = 1.f / L;
    }
    __syncthreads();

#pragma unroll
    for (int i = 0; i < 4; i++) {
        int idx = tid + i * 256;           // 0..1023 float4 slots
        int row = idx >> 4;
        int c4  = (idx & 15) * 4;
        float4 acc = make_float4(0.f, 0.f, 0.f, 0.f);
        for (int c = 0; c < nc; c++) {
            float4 v = *(const float4*)&g_po[(pbase + c) * 4096 + row * 64 + c4];
            float wi = w[c][row];
            acc.x = fmaf(wi, v.x, acc.x);
            acc.y = fmaf(wi, v.y, acc.y);
            acc.z = fmaf(wi, v.z, acc.z);
            acc.w = fmaf(wi, v.w, acc.w);
        }
        float inv = invL[row];
        acc.x *= inv; acc.y *= inv; acc.z *= inv; acc.w *= inv;
        *(float4*)&out[((size_t)bb * SEQ + qt * 64 + row) * HS + c4] = acc;
    }
}

// ---------------------------------------------------------------------------
extern "C" void kernel_launch(void* const* d_in, const int* in_sizes, int n_in,
                              void* d_out, int out_size)
{
    const float* xq  = (const float*)d_in[0];
    const float* xkv = (const float*)d_in[1];
    const float* Wq  = (const float*)d_in[2];
    const float* Wk  = (const float*)d_in[3];
    const float* Wv  = (const float*)d_in[4];
    float* out = (float*)d_out;

    qkv_kernel<<<dim3(M_TOTAL / QKV_BM, 3), 128>>>(xq, xkv, Wq, Wk, Wv);
    attn_partial<<<dim3(NQT, NCHUNK, BATCH), 256>>>();
    attn_reduce<<<dim3(NQT, BATCH), 256>>>(out);
}

// round 6
// speedup vs baseline: 1.9449x; 1.9449x over previous
#include <cuda_runtime.h>
#include <math.h>
#include <stdint.h>

#define BATCH 8
#define SEQ   2048
#define CDIM  1024
#define HS    64
#define M_TOTAL (BATCH * SEQ)   // 16384

#define NQT    (SEQ / 64)       // 32 query tiles per batch
#define NCHUNK 8                // 8 KV chunks of 256 keys (4 tiles of 64)

// Scratch (device globals: allowed).
__device__ float g_q[M_TOTAL * HS];
__device__ float g_k[M_TOTAL * HS];
__device__ float g_v[M_TOTAL * HS];
// Split-KV partials: [B][NQT][NCHUNK][64 rows][64 cols] + per-row m,l
__device__ float g_po[(size_t)BATCH * NQT * NCHUNK * 64 * 64];
__device__ float g_pm[BATCH * NQT * NCHUNK * 64];
__device__ float g_pl[BATCH * NQT * NCHUNK * 64];

// ---------------------------------------------------------------------------
// helpers
// ---------------------------------------------------------------------------
__device__ __forceinline__ float tf32r(float x) {
    uint32_t u;
    asm("cvt.rna.tf32.f32 %0, %1;" : "=r"(u) : "f"(x));
    return __uint_as_float(u);
}

__device__ __forceinline__ void mma_tf32(float4& d, const float* a, const float* b) {
    asm volatile(
        "mma.sync.aligned.m16n8k8.row.col.f32.tf32.tf32.f32 "
        "{%0,%1,%2,%3}, {%4,%5,%6,%7}, {%8,%9}, {%0,%1,%2,%3};"
        : "+f"(d.x), "+f"(d.y), "+f"(d.z), "+f"(d.w)
        : "r"(__float_as_uint(a[0])), "r"(__float_as_uint(a[1])),
          "r"(__float_as_uint(a[2])), "r"(__float_as_uint(a[3])),
          "r"(__float_as_uint(b[0])), "r"(__float_as_uint(b[1])));
}

__device__ __forceinline__ void cpa16(void* smem_dst, const void* gmem_src) {
    uint32_t s = (uint32_t)__cvta_generic_to_shared(smem_dst);
    asm volatile("cp.async.cg.shared.global [%0], [%1], 16;" :: "r"(s), "l"(gmem_src));
}
#define CP_COMMIT() asm volatile("cp.async.commit_group;")
#define CP_WAIT(n)  asm volatile("cp.async.wait_group %0;" :: "n"(n))

// ---------------------------------------------------------------------------
// Kernel 1: QKV projection with 3xTF32 tensor-core GEMM.
// [M_TOTAL,CDIM] x [CDIM,HS] -> [M_TOTAL,HS].
// grid = (M_TOTAL/128, 3), block = 128 (4 warps).
// CTA tile 128x64, BK=16; warp w owns rows w*32..+31, all 64 cols.
// smem: raw fp32, double-buffered, fed by cp.async; hi/lo tf32 split at
// fragment load. 3 mma per position: hi*hi + hi*lo + lo*hi (fp32-grade).
// ---------------------------------------------------------------------------
#define QBM 128
#define QBK 16
#define A_STR 20     // padded row stride (floats) for As[m][k]
#define B_STR 72     // padded row stride (floats) for Bs[k][n]
#define NKITER (CDIM / QBK)   // 64

__global__ __launch_bounds__(128) void qkv_tc(
    const float* __restrict__ xq, const float* __restrict__ xkv,
    const float* __restrict__ Wq, const float* __restrict__ Wk,
    const float* __restrict__ Wv)
{
    const int which = blockIdx.y;                 // 0=Q, 1=K, 2=V
    const float* __restrict__ X = (which == 0) ? xq : xkv;
    const float* __restrict__ W = (which == 0) ? Wq : (which == 1 ? Wk : Wv);
    float* __restrict__ O = (which == 0) ? g_q : (which == 1 ? g_k : g_v);

    __shared__ __align__(16) float As[2][QBM][A_STR];
    __shared__ __align__(16) float Bs[2][QBK][B_STR];

    const int tid  = threadIdx.x;
    const int warp = tid >> 5;
    const int lane = tid & 31;
    const int m0   = blockIdx.x * QBM;

    float4 acc[2][8];
#pragma unroll
    for (int mt = 0; mt < 2; mt++)
#pragma unroll
        for (int nt = 0; nt < 8; nt++) acc[mt][nt] = make_float4(0.f, 0.f, 0.f, 0.f);

    // tile loader: A 128x16 (4 cpa16/thr), B 16x64 (2 cpa16/thr)
    auto load_tile = [&](int it, int buf) {
        const int k0 = it * QBK;
#pragma unroll
        for (int i = 0; i < 4; i++) {
            int idx = tid + i * 128;       // 0..511
            int r   = idx >> 2;
            int c4  = (idx & 3) * 4;
            cpa16(&As[buf][r][c4], &X[(size_t)(m0 + r) * CDIM + k0 + c4]);
        }
#pragma unroll
        for (int i = 0; i < 2; i++) {
            int idx = tid + i * 128;       // 0..255
            int r   = idx >> 4;
            int c4  = (idx & 15) * 4;
            cpa16(&Bs[buf][r][c4], &W[(size_t)(k0 + r) * HS + c4]);
        }
    };

    load_tile(0, 0);
    CP_COMMIT();

    const int arow = warp * 32 + (lane >> 2);   // fragment base row (local)
    const int kq   = lane & 3;                  // quad column
    const int bcol = lane >> 2;                 // B fragment column

    for (int it = 0; it < NKITER; it++) {
        const int buf = it & 1;
        if (it + 1 < NKITER) {
            load_tile(it + 1, buf ^ 1);
            CP_COMMIT();
            CP_WAIT(1);
        } else {
            CP_WAIT(0);
        }
        __syncthreads();

#pragma unroll
        for (int kk = 0; kk < 2; kk++) {
            const int ks = kk * 8;
            // A fragments: raw -> hi/lo
            float ah[2][4], al[2][4];
#pragma unroll
            for (int mt = 0; mt < 2; mt++) {
                const int r = arow + mt * 16;
                float raw[4];
                raw[0] = As[buf][r][ks + kq];
                raw[1] = As[buf][r + 8][ks + kq];
                raw[2] = As[buf][r][ks + kq + 4];
                raw[3] = As[buf][r + 8][ks + kq + 4];
#pragma unroll
                for (int i = 0; i < 4; i++) {
                    ah[mt][i] = tf32r(raw[i]);
                    al[mt][i] = tf32r(raw[i] - ah[mt][i]);
                }
            }
#pragma unroll
            for (int nt = 0; nt < 8; nt++) {
                float braw0 = Bs[buf][ks + kq][nt * 8 + bcol];
                float braw1 = Bs[buf][ks + kq + 4][nt * 8 + bcol];
                float bh[2], bl[2];
                bh[0] = tf32r(braw0); bl[0] = tf32r(braw0 - bh[0]);
                bh[1] = tf32r(braw1); bl[1] = tf32r(braw1 - bh[1]);
#pragma unroll
                for (int mt = 0; mt < 2; mt++) {
                    mma_tf32(acc[mt][nt], ah[mt], bh);
                    mma_tf32(acc[mt][nt], ah[mt], bl);
                    mma_tf32(acc[mt][nt], al[mt], bh);
                }
            }
        }
        __syncthreads();
    }

    // Epilogue: C fragment rows {l/4, l/4+8}, cols {2*(l%4), +1} per tile.
#pragma unroll
    for (int mt = 0; mt < 2; mt++) {
        const int row0 = m0 + warp * 32 + mt * 16 + (lane >> 2);
#pragma unroll
        for (int nt = 0; nt < 8; nt++) {
            const int col = nt * 8 + 2 * (lane & 3);
            *(float2*)&O[(size_t)row0 * HS + col] =
                make_float2(acc[mt][nt].x, acc[mt][nt].y);
            *(float2*)&O[(size_t)(row0 + 8) * HS + col] =
                make_float2(acc[mt][nt].z, acc[mt][nt].w);
        }
    }
}

// ---------------------------------------------------------------------------
// Kernel 2: split-KV causal flash attention (partials).
// grid = (NQT, NCHUNK, BATCH), block = 256. Each CTA: one 64-row Q tile x
// one 256-key chunk (<=4 KV tiles). Writes unnormalized o + (m, l).
// ---------------------------------------------------------------------------
__global__ __launch_bounds__(256) void attn_partial(void)
{
    const int qt  = blockIdx.x;            // 0..31
    const int cix = blockIdx.y;            // 0..7
    const int bb  = blockIdx.z;            // 0..7
    if (cix * 4 > qt) return;              // chunk entirely above diagonal

    __shared__ float Qs[64][64];    // Qs[i][h]
    __shared__ float KVs[64][64];   // first K^T: KVs[h][j]; then V: KVs[k][j]
    __shared__ float Ps[64][64];    // P[i][j]

    const int tid = threadIdx.x;
    const int tx  = tid & 15;
    const int ty  = tid >> 4;
    const int i0  = ty * 4;
    const int j0  = tx * 4;

    const float scale = 0.03125f;          // 1024^-0.5

    const float* Qg = g_q + ((size_t)bb * SEQ + qt * 64) * HS;
#pragma unroll
    for (int i = 0; i < 4; i++) {
        int idx = tid + i * 256;
        int r   = idx >> 4;
        int c4  = (idx & 15) * 4;
        *(float4*)&Qs[r][c4] = *(const float4*)&Qg[r * HS + c4];
    }

    float o[4][4];
    float m_run[4], l_run[4];
#pragma unroll
    for (int r = 0; r < 4; r++) {
        m_run[r] = -INFINITY;
        l_run[r] = 0.f;
#pragma unroll
        for (int c = 0; c < 4; c++) o[r][c] = 0.f;
    }

    const int kt_begin = cix * 4;
    const int kt_end   = (cix * 4 + 3 < qt) ? (cix * 4 + 3) : qt;

    for (int kt = kt_begin; kt <= kt_end; kt++) {
        const float* Kg = g_k + ((size_t)bb * SEQ + kt * 64) * HS;
        const float* Vg = g_v + ((size_t)bb * SEQ + kt * 64) * HS;

        // K tile transposed: KVs[h][j].
#pragma unroll
        for (int i = 0; i < 4; i++) {
            int idx = tid + i * 256;
            int r   = idx >> 4;
            int c4  = (idx & 15) * 4;
            float4 v = *(const float4*)&Kg[r * HS + c4];
            KVs[c4 + 0][r] = v.x;
            KVs[c4 + 1][r] = v.y;
            KVs[c4 + 2][r] = v.z;
            KVs[c4 + 3][r] = v.w;
        }
        __syncthreads();

        float s[4][4];
#pragma unroll
        for (int r = 0; r < 4; r++)
#pragma unroll
            for (int c = 0; c < 4; c++) s[r][c] = 0.f;

        for (int h = 0; h < 64; h++) {
            float4 bv = *(const float4*)&KVs[h][j0];
            float a0 = Qs[i0 + 0][h];
            float a1 = Qs[i0 + 1][h];
            float a2 = Qs[i0 + 2][h];
            float a3 = Qs[i0 + 3][h];
            s[0][0] = fmaf(a0, bv.x, s[0][0]); s[0][1] = fmaf(a0, bv.y, s[0][1]);
            s[0][2] = fmaf(a0, bv.z, s[0][2]); s[0][3] = fmaf(a0, bv.w, s[0][3]);
            s[1][0] = fmaf(a1, bv.x, s[1][0]); s[1][1] = fmaf(a1, bv.y, s[1][1]);
            s[1][2] = fmaf(a1, bv.z, s[1][2]); s[1][3] = fmaf(a1, bv.w, s[1][3]);
            s[2][0] = fmaf(a2, bv.x, s[2][0]); s[2][1] = fmaf(a2, bv.y, s[2][1]);
            s[2][2] = fmaf(a2, bv.z, s[2][2]); s[2][3] = fmaf(a2, bv.w, s[2][3]);
            s[3][0] = fmaf(a3, bv.x, s[3][0]); s[3][1] = fmaf(a3, bv.y, s[3][1]);
            s[3][2] = fmaf(a3, bv.z, s[3][2]); s[3][3] = fmaf(a3, bv.w, s[3][3]);
        }

        const bool diag = (kt == qt);
#pragma unroll
        for (int r = 0; r < 4; r++)
#pragma unroll
            for (int c = 0; c < 4; c++) {
                float sv = s[r][c] * scale;
                if (diag && (j0 + c) > (i0 + r)) sv = -INFINITY;
                s[r][c] = sv;
            }

        float rmax[4];
#pragma unroll
        for (int r = 0; r < 4; r++)
            rmax[r] = fmaxf(fmaxf(s[r][0], s[r][1]), fmaxf(s[r][2], s[r][3]));
#pragma unroll
        for (int off = 8; off > 0; off >>= 1)
#pragma unroll
            for (int r = 0; r < 4; r++)
                rmax[r] = fmaxf(rmax[r], __shfl_xor_sync(0xffffffffu, rmax[r], off));

        float alpha[4];
#pragma unroll
        for (int r = 0; r < 4; r++) {
            float mn = fmaxf(m_run[r], rmax[r]);
            alpha[r] = __expf(m_run[r] - mn);
            m_run[r] = mn;
        }

        float rsum[4] = {0.f, 0.f, 0.f, 0.f};
#pragma unroll
        for (int r = 0; r < 4; r++)
#pragma unroll
            for (int c = 0; c < 4; c++) {
                float p = __expf(s[r][c] - m_run[r]);
                Ps[i0 + r][j0 + c] = p;
                rsum[r] += p;
            }
#pragma unroll
        for (int off = 8; off > 0; off >>= 1)
#pragma unroll
            for (int r = 0; r < 4; r++)
                rsum[r] += __shfl_xor_sync(0xffffffffu, rsum[r], off);

#pragma unroll
        for (int r = 0; r < 4; r++) {
            l_run[r] = l_run[r] * alpha[r] + rsum[r];
#pragma unroll
            for (int c = 0; c < 4; c++) o[r][c] *= alpha[r];
        }

        __syncthreads();

        // V tile: KVs[k][j].
#pragma unroll
        for (int i = 0; i < 4; i++) {
            int idx = tid + i * 256;
            int r   = idx >> 4;
            int c4  = (idx & 15) * 4;
            *(float4*)&KVs[r][c4] = *(const float4*)&Vg[r * HS + c4];
        }
        __syncthreads();

        for (int k = 0; k < 64; k++) {
            float4 bv = *(const float4*)&KVs[k][j0];
            float p0 = Ps[i0 + 0][k];
            float p1 = Ps[i0 + 1][k];
            float p2 = Ps[i0 + 2][k];
            float p3 = Ps[i0 + 3][k];
            o[0][0] = fmaf(p0, bv.x, o[0][0]); o[0][1] = fmaf(p0, bv.y, o[0][1]);
            o[0][2] = fmaf(p0, bv.z, o[0][2]); o[0][3] = fmaf(p0, bv.w, o[0][3]);
            o[1][0] = fmaf(p1, bv.x, o[1][0]); o[1][1] = fmaf(p1, bv.y, o[1][1]);
            o[1][2] = fmaf(p1, bv.z, o[1][2]); o[1][3] = fmaf(p1, bv.w, o[1][3]);
            o[2][0] = fmaf(p2, bv.x, o[2][0]); o[2][1] = fmaf(p2, bv.y, o[2][1]);
            o[2][2] = fmaf(p2, bv.z, o[2][2]); o[2][3] = fmaf(p2, bv.w, o[2][3]);
            o[3][0] = fmaf(p3, bv.x, o[3][0]); o[3][1] = fmaf(p3, bv.y, o[3][1]);
            o[3][2] = fmaf(p3, bv.z, o[3][2]); o[3][3] = fmaf(p3, bv.w, o[3][3]);
        }
        __syncthreads();
    }

    // Store partials (unnormalized o, plus m, l).
    const size_t p = ((size_t)(bb * NQT + qt) * NCHUNK + cix);
#pragma unroll
    for (int r = 0; r < 4; r++) {
        *(float4*)&g_po[p * 4096 + (i0 + r) * 64 + j0] =
            make_float4(o[r][0], o[r][1], o[r][2], o[r][3]);
    }
    if (tx == 0) {
#pragma unroll
        for (int r = 0; r < 4; r++) {
            g_pm[p * 64 + i0 + r] = m_run[r];
            g_pl[p * 64 + i0 + r] = l_run[r];
        }
    }
}

// ---------------------------------------------------------------------------
// Kernel 3: combine split-KV partials. grid = (NQT, BATCH), block = 256.
// ---------------------------------------------------------------------------
__global__ __launch_bounds__(256) void attn_reduce(float* __restrict__ out)
{
    const int qt = blockIdx.x;
    const int bb = blockIdx.y;
    const int nc = qt / 4 + 1;             // chunks touching this q tile

    __shared__ float w[NCHUNK][64];
    __shared__ float invL[64];

    const int tid = threadIdx.x;
    const size_t pbase = (size_t)(bb * NQT + qt) * NCHUNK;

    if (tid < 64) {
        const int row = tid;
        float M = -INFINITY;
        for (int c = 0; c < nc; c++)
            M = fmaxf(M, g_pm[(pbase + c) * 64 + row]);
        float L = 0.f;
        for (int c = 0; c < nc; c++) {
            float wi = __expf(g_pm[(pbase + c) * 64 + row] - M);
            w[c][row] = wi;
            L += wi * g_pl[(pbase + c) * 64 + row];
        }
        invL[row] = 1.f / L;
    }
    __syncthreads();

#pragma unroll
    for (int i = 0; i < 4; i++) {
        int idx = tid + i * 256;           // 0..1023 float4 slots
        int row = idx >> 4;
        int c4  = (idx & 15) * 4;
        float4 acc = make_float4(0.f, 0.f, 0.f, 0.f);
        for (int c = 0; c < nc; c++) {
            float4 v = *(const float4*)&g_po[(pbase + c) * 4096 + row * 64 + c4];
            float wi = w[c][row];
            acc.x = fmaf(wi, v.x, acc.x);
            acc.y = fmaf(wi, v.y, acc.y);
            acc.z = fmaf(wi, v.z, acc.z);
            acc.w = fmaf(wi, v.w, acc.w);
        }
        float inv = invL[row];
        acc.x *= inv; acc.y *= inv; acc.z *= inv; acc.w *= inv;
        *(float4*)&out[((size_t)bb * SEQ + qt * 64 + row) * HS + c4] = acc;
    }
}

// ---------------------------------------------------------------------------
extern "C" void kernel_launch(void* const* d_in, const int* in_sizes, int n_in,
                              void* d_out, int out_size)
{
    const float* xq  = (const float*)d_in[0];
    const float* xkv = (const float*)d_in[1];
    const float* Wq  = (const float*)d_in[2];
    const float* Wk  = (const float*)d_in[3];
    const float* Wv  = (const float*)d_in[4];
    float* out = (float*)d_out;

    qkv_tc<<<dim3(M_TOTAL / QBM, 3), 128>>>(xq, xkv, Wq, Wk, Wv);
    attn_partial<<<dim3(NQT, NCHUNK, BATCH), 256>>>();
    attn_reduce<<<dim3(NQT, BATCH), 256>>>(out);
}

// round 7
// speedup vs baseline: 2.5954x; 1.3344x over previous
#include <cuda_runtime.h>
#include <math.h>
#include <stdint.h>

#define BATCH 8
#define SEQ   2048
#define CDIM  1024
#define HS    64
#define M_TOTAL (BATCH * SEQ)   // 16384

#define NQT    (SEQ / 64)       // 32 query tiles per batch
#define NCHUNK 8                // 8 KV chunks of 256 keys (4 tiles of 64)

// Scratch (device globals: allowed).
__device__ float g_q[M_TOTAL * HS];
__device__ float g_k[M_TOTAL * HS];
__device__ float g_v[M_TOTAL * HS];
__device__ float g_po[(size_t)BATCH * NQT * NCHUNK * 64 * 64];
__device__ float g_pm[BATCH * NQT * NCHUNK * 64];
__device__ float g_pl[BATCH * NQT * NCHUNK * 64];
// Pre-split weights (tf32 hi/lo), layout [which][k][n]
__device__ float g_wh[3 * CDIM * HS];
__device__ float g_wl[3 * CDIM * HS];

// ---------------------------------------------------------------------------
// helpers
// ---------------------------------------------------------------------------
__device__ __forceinline__ float tf32r(float x) {
    uint32_t u;
    asm("cvt.rna.tf32.f32 %0, %1;" : "=r"(u) : "f"(x));
    return __uint_as_float(u);
}

__device__ __forceinline__ void mma_tf32(float4& d, const float* a, const float* b) {
    asm volatile(
        "mma.sync.aligned.m16n8k8.row.col.f32.tf32.tf32.f32 "
        "{%0,%1,%2,%3}, {%4,%5,%6,%7}, {%8,%9}, {%0,%1,%2,%3};"
        : "+f"(d.x), "+f"(d.y), "+f"(d.z), "+f"(d.w)
        : "r"(__float_as_uint(a[0])), "r"(__float_as_uint(a[1])),
          "r"(__float_as_uint(a[2])), "r"(__float_as_uint(a[3])),
          "r"(__float_as_uint(b[0])), "r"(__float_as_uint(b[1])));
}

__device__ __forceinline__ void cpa16(void* smem_dst, const void* gmem_src) {
    uint32_t s = (uint32_t)__cvta_generic_to_shared(smem_dst);
    asm volatile("cp.async.cg.shared.global [%0], [%1], 16;" :: "r"(s), "l"(gmem_src));
}
#define CP_COMMIT() asm volatile("cp.async.commit_group;")
#define CP_WAIT(n)  asm volatile("cp.async.wait_group %0;" :: "n"(n))

// ---------------------------------------------------------------------------
// Kernel 0: split W into tf32 hi/lo. 3*1024*64 = 196608 floats = 49152 float4.
// grid = 192, block = 256 -> one float4 per thread.
// ---------------------------------------------------------------------------
__global__ __launch_bounds__(256) void wsplit(
    const float* __restrict__ Wq, const float* __restrict__ Wk,
    const float* __restrict__ Wv)
{
    const int idx = blockIdx.x * 256 + threadIdx.x;      // float4 id, 0..49151
    const float* W = (idx < 16384) ? Wq : (idx < 32768 ? Wk : Wv);
    const int local = (idx & 16383) * 4;
    float4 w = *(const float4*)&W[local];
    float4 h, l;
    h.x = tf32r(w.x); l.x = tf32r(w.x - h.x);
    h.y = tf32r(w.y); l.y = tf32r(w.y - h.y);
    h.z = tf32r(w.z); l.z = tf32r(w.z - h.z);
    h.w = tf32r(w.w); l.w = tf32r(w.w - h.w);
    *(float4*)&g_wh[idx * 4] = h;
    *(float4*)&g_wl[idx * 4] = l;
}

// ---------------------------------------------------------------------------
// Kernel 1: QKV projection, 3xTF32 mma. B (weights) pre-split -> no B cvt.
// ---------------------------------------------------------------------------
#define QBM 128
#define QBK 16
#define A_STR 20
#define B_STR 72
#define NKITER (CDIM / QBK)   // 64

__global__ __launch_bounds__(128) void qkv_tc(
    const float* __restrict__ xq, const float* __restrict__ xkv)
{
    const int which = blockIdx.y;                 // 0=Q, 1=K, 2=V
    const float* __restrict__ X  = (which == 0) ? xq : xkv;
    const float* __restrict__ WH = g_wh + which * CDIM * HS;
    const float* __restrict__ WL = g_wl + which * CDIM * HS;
    float* __restrict__ O = (which == 0) ? g_q : (which == 1 ? g_k : g_v);

    __shared__ __align__(16) float As[2][QBM][A_STR];
    __shared__ __align__(16) float Bh[2][QBK][B_STR];
    __shared__ __align__(16) float Bl[2][QBK][B_STR];

    const int tid  = threadIdx.x;
    const int warp = tid >> 5;
    const int lane = tid & 31;
    const int m0   = blockIdx.x * QBM;

    float4 acc[2][8];
#pragma unroll
    for (int mt = 0; mt < 2; mt++)
#pragma unroll
        for (int nt = 0; nt < 8; nt++) acc[mt][nt] = make_float4(0.f, 0.f, 0.f, 0.f);

    auto load_tile = [&](int it, int buf) {
        const int k0 = it * QBK;
#pragma unroll
        for (int i = 0; i < 4; i++) {
            int idx = tid + i * 128;       // 0..511
            int r   = idx >> 2;
            int c4  = (idx & 3) * 4;
            cpa16(&As[buf][r][c4], &X[(size_t)(m0 + r) * CDIM + k0 + c4]);
        }
#pragma unroll
        for (int i = 0; i < 2; i++) {
            int idx = tid + i * 128;       // 0..255
            int r   = idx >> 4;
            int c4  = (idx & 15) * 4;
            cpa16(&Bh[buf][r][c4], &WH[(size_t)(k0 + r) * HS + c4]);
            cpa16(&Bl[buf][r][c4], &WL[(size_t)(k0 + r) * HS + c4]);
        }
    };

    load_tile(0, 0);
    CP_COMMIT();

    const int arow = warp * 32 + (lane >> 2);
    const int kq   = lane & 3;
    const int bcol = lane >> 2;

    for (int it = 0; it < NKITER; it++) {
        const int buf = it & 1;
        if (it + 1 < NKITER) {
            load_tile(it + 1, buf ^ 1);
            CP_COMMIT();
            CP_WAIT(1);
        } else {
            CP_WAIT(0);
        }
        __syncthreads();

#pragma unroll
        for (int kk = 0; kk < 2; kk++) {
            const int ks = kk * 8;
            float ah[2][4], al[2][4];
#pragma unroll
            for (int mt = 0; mt < 2; mt++) {
                const int r = arow + mt * 16;
                float raw[4];
                raw[0] = As[buf][r][ks + kq];
                raw[1] = As[buf][r + 8][ks + kq];
                raw[2] = As[buf][r][ks + kq + 4];
                raw[3] = As[buf][r + 8][ks + kq + 4];
#pragma unroll
                for (int i = 0; i < 4; i++) {
                    ah[mt][i] = tf32r(raw[i]);
                    al[mt][i] = tf32r(raw[i] - ah[mt][i]);
                }
            }
#pragma unroll
            for (int nt = 0; nt < 8; nt++) {
                float bh[2], bl[2];
                bh[0] = Bh[buf][ks + kq][nt * 8 + bcol];
                bh[1] = Bh[buf][ks + kq + 4][nt * 8 + bcol];
                bl[0] = Bl[buf][ks + kq][nt * 8 + bcol];
                bl[1] = Bl[buf][ks + kq + 4][nt * 8 + bcol];
#pragma unroll
                for (int mt = 0; mt < 2; mt++) {
                    mma_tf32(acc[mt][nt], ah[mt], bh);
                    mma_tf32(acc[mt][nt], ah[mt], bl);
                    mma_tf32(acc[mt][nt], al[mt], bh);
                }
            }
        }
        __syncthreads();
    }

#pragma unroll
    for (int mt = 0; mt < 2; mt++) {
        const int row0 = m0 + warp * 32 + mt * 16 + (lane >> 2);
#pragma unroll
        for (int nt = 0; nt < 8; nt++) {
            const int col = nt * 8 + 2 * (lane & 3);
            *(float2*)&O[(size_t)row0 * HS + col] =
                make_float2(acc[mt][nt].x, acc[mt][nt].y);
            *(float2*)&O[(size_t)(row0 + 8) * HS + col] =
                make_float2(acc[mt][nt].z, acc[mt][nt].w);
        }
    }
}

// ---------------------------------------------------------------------------
// Kernel 2: split-KV causal flash attention with tf32 mma (3-term splits).
// grid = (NQT, NCHUNK, BATCH), block = 128 (4 warps).
// Warp w: rows 16w..16w+15 of the 64-row Q tile, all 64 cols.
// smem (dynamic): KVh[64][AST], KVl[64][AST] (K then V per kt), Ps[64][AST].
// K stored with column-pair permutation so B-frags load as LDS.64.
// ---------------------------------------------------------------------------
#define AST 68

__global__ __launch_bounds__(128) void attn_tc(void)
{
    extern __shared__ float sm[];
    float* KVh = sm;                    // [64][AST]
    float* KVl = sm + 64 * AST;         // [64][AST]
    float* Ps  = sm + 2 * 64 * AST;     // [64][AST]

    const int qt  = blockIdx.x;
    const int cix = blockIdx.y;
    const int bb  = blockIdx.z;
    if (cix * 4 > qt) return;

    const int tid  = threadIdx.x;
    const int warp = tid >> 5;
    const int lane = tid & 31;
    const int r    = lane >> 2;        // 0..7 (fragment row / B col)
    const int kq   = lane & 3;         // quad k
    const float scale = 0.03125f;      // 1024^-0.5

    // ---- Q fragments hoisted: rows warp*16 + r (+8), k = 8ks+kq (+4)
    float qh[8][4], ql[8][4];
    {
        const float* Qg = g_q + ((size_t)bb * SEQ + qt * 64 + warp * 16) * HS;
#pragma unroll
        for (int ks = 0; ks < 8; ks++) {
            float raw[4];
            raw[0] = Qg[r * HS + 8 * ks + kq];
            raw[1] = Qg[(r + 8) * HS + 8 * ks + kq];
            raw[2] = Qg[r * HS + 8 * ks + kq + 4];
            raw[3] = Qg[(r + 8) * HS + 8 * ks + kq + 4];
#pragma unroll
            for (int i = 0; i < 4; i++) {
                qh[ks][i] = tf32r(raw[i]);
                ql[ks][i] = tf32r(raw[i] - qh[ks][i]);
            }
        }
    }

    float4 o[8];
#pragma unroll
    for (int nt = 0; nt < 8; nt++) o[nt] = make_float4(0.f, 0.f, 0.f, 0.f);
    float m_lo = -INFINITY, m_hi = -INFINITY, l_lo = 0.f, l_hi = 0.f;

    const int kt_begin = cix * 4;
    const int kt_end   = (cix * 4 + 3 < qt) ? (cix * 4 + 3) : qt;

    for (int kt = kt_begin; kt <= kt_end; kt++) {
        const float* Kg = g_k + ((size_t)bb * SEQ + kt * 64) * HS;
        const float* Vg = g_v + ((size_t)bb * SEQ + kt * 64) * HS;

        __syncthreads();   // prev-iter V reads (PV) done before K overwrite

        // ---- K load + tf32 split, permuted columns: h -> (h&~7)|((h&3)<<1)|((h>>2)&1)
#pragma unroll
        for (int i = 0; i < 8; i++) {
            int idx = tid + i * 128;   // float4 id 0..1023
            int row = idx >> 4;
            int c4  = (idx & 15) * 4;
            float4 v = *(const float4*)&Kg[row * HS + c4];
            float vals[4] = {v.x, v.y, v.z, v.w};
#pragma unroll
            for (int j = 0; j < 4; j++) {
                int h = c4 + j;
                int p = (h & ~7) | ((h & 3) << 1) | ((h >> 2) & 1);
                float hi = tf32r(vals[j]);
                KVh[row * AST + p] = hi;
                KVl[row * AST + p] = tf32r(vals[j] - hi);
            }
        }
        __syncthreads();

        // ---- S = Q K^T (3-term)
        float4 s[8];
#pragma unroll
        for (int nt = 0; nt < 8; nt++) s[nt] = make_float4(0.f, 0.f, 0.f, 0.f);

#pragma unroll
        for (int ks = 0; ks < 8; ks++) {
#pragma unroll
            for (int nt = 0; nt < 8; nt++) {
                const int jrow = nt * 8 + r;
                float2 bh = *(const float2*)&KVh[jrow * AST + 8 * ks + 2 * kq];
                float2 bl = *(const float2*)&KVl[jrow * AST + 8 * ks + 2 * kq];
                mma_tf32(s[nt], qh[ks], (const float*)&bh);
                mma_tf32(s[nt], qh[ks], (const float*)&bl);
                mma_tf32(s[nt], ql[ks], (const float*)&bh);
            }
        }

        // ---- scale + causal mask (fragment rows: lo = warp*16+r, hi = +8)
        const bool diag = (kt == qt);
        const int irow_lo = warp * 16 + r;
        const int irow_hi = irow_lo + 8;
#pragma unroll
        for (int nt = 0; nt < 8; nt++) {
            const int c0 = nt * 8 + 2 * kq;
            s[nt].x *= scale; s[nt].y *= scale;
            s[nt].z *= scale; s[nt].w *= scale;
            if (diag) {
                if (c0     > irow_lo) s[nt].x = -INFINITY;
                if (c0 + 1 > irow_lo) s[nt].y = -INFINITY;
                if (c0     > irow_hi) s[nt].z = -INFINITY;
                if (c0 + 1 > irow_hi) s[nt].w = -INFINITY;
            }
        }

        // ---- row max over 64 cols: local 16 + shuffle over 4-lane group
        float rmax_lo = -INFINITY, rmax_hi = -INFINITY;
#pragma unroll
        for (int nt = 0; nt < 8; nt++) {
            rmax_lo = fmaxf(rmax_lo, fmaxf(s[nt].x, s[nt].y));
            rmax_hi = fmaxf(rmax_hi, fmaxf(s[nt].z, s[nt].w));
        }
        rmax_lo = fmaxf(rmax_lo, __shfl_xor_sync(0xffffffffu, rmax_lo, 1));
        rmax_lo = fmaxf(rmax_lo, __shfl_xor_sync(0xffffffffu, rmax_lo, 2));
        rmax_hi = fmaxf(rmax_hi, __shfl_xor_sync(0xffffffffu, rmax_hi, 1));
        rmax_hi = fmaxf(rmax_hi, __shfl_xor_sync(0xffffffffu, rmax_hi, 2));

        float mn_lo = fmaxf(m_lo, rmax_lo);
        float mn_hi = fmaxf(m_hi, rmax_hi);
        float alpha_lo = __expf(m_lo - mn_lo);
        float alpha_hi = __expf(m_hi - mn_hi);
        m_lo = mn_lo; m_hi = mn_hi;

        // ---- p = exp(s - m), write raw P to smem (own rows only), row sums
        float rsum_lo = 0.f, rsum_hi = 0.f;
#pragma unroll
        for (int nt = 0; nt < 8; nt++) {
            const int c0 = nt * 8 + 2 * kq;
            float px = __expf(s[nt].x - m_lo);
            float py = __expf(s[nt].y - m_lo);
            float pz = __expf(s[nt].z - m_hi);
            float pw = __expf(s[nt].w - m_hi);
            rsum_lo += px + py;
            rsum_hi += pz + pw;
            *(float2*)&Ps[irow_lo * AST + c0] = make_float2(px, py);
            *(float2*)&Ps[irow_hi * AST + c0] = make_float2(pz, pw);
        }
        rsum_lo += __shfl_xor_sync(0xffffffffu, rsum_lo, 1);
        rsum_lo += __shfl_xor_sync(0xffffffffu, rsum_lo, 2);
        rsum_hi += __shfl_xor_sync(0xffffffffu, rsum_hi, 1);
        rsum_hi += __shfl_xor_sync(0xffffffffu, rsum_hi, 2);

        l_lo = l_lo * alpha_lo + rsum_lo;
        l_hi = l_hi * alpha_hi + rsum_hi;
#pragma unroll
        for (int nt = 0; nt < 8; nt++) {
            o[nt].x *= alpha_lo; o[nt].y *= alpha_lo;
            o[nt].z *= alpha_hi; o[nt].w *= alpha_hi;
        }

        __syncthreads();   // all warps done reading K before V overwrite

        // ---- V load + tf32 split (natural layout [j][col])
#pragma unroll
        for (int i = 0; i < 8; i++) {
            int idx = tid + i * 128;
            int row = idx >> 4;
            int c4  = (idx & 15) * 4;
            float4 v = *(const float4*)&Vg[row * HS + c4];
            float4 h4, l4;
            h4.x = tf32r(v.x); l4.x = tf32r(v.x - h4.x);
            h4.y = tf32r(v.y); l4.y = tf32r(v.y - h4.y);
            h4.z = tf32r(v.z); l4.z = tf32r(v.z - h4.z);
            h4.w = tf32r(v.w); l4.w = tf32r(v.w - h4.w);
            *(float4*)&KVh[row * AST + c4] = h4;
            *(float4*)&KVl[row * AST + c4] = l4;
        }
        __syncthreads();

        // ---- O += P V (3-term; P raw split at read, same-warp rows)
#pragma unroll
        for (int ks = 0; ks < 8; ks++) {
            float raw[4];
            raw[0] = Ps[irow_lo * AST + 8 * ks + kq];
            raw[1] = Ps[irow_hi * AST + 8 * ks + kq];
            raw[2] = Ps[irow_lo * AST + 8 * ks + kq + 4];
            raw[3] = Ps[irow_hi * AST + 8 * ks + kq + 4];
            float ah[4], al[4];
#pragma unroll
            for (int i = 0; i < 4; i++) {
                ah[i] = tf32r(raw[i]);
                al[i] = tf32r(raw[i] - ah[i]);
            }
#pragma unroll
            for (int nt = 0; nt < 8; nt++) {
                float bh[2], bl[2];
                bh[0] = KVh[(8 * ks + kq) * AST + nt * 8 + r];
                bh[1] = KVh[(8 * ks + kq + 4) * AST + nt * 8 + r];
                bl[0] = KVl[(8 * ks + kq) * AST + nt * 8 + r];
                bl[1] = KVl[(8 * ks + kq + 4) * AST + nt * 8 + r];
                mma_tf32(o[nt], ah, bh);
                mma_tf32(o[nt], ah, bl);
                mma_tf32(o[nt], al, bh);
            }
        }
    }

    // ---- store partials (unnormalized) + m, l
    const size_t p = ((size_t)(bb * NQT + qt) * NCHUNK + cix);
    const int irow_lo = warp * 16 + (lane >> 2);
    const int irow_hi = irow_lo + 8;
#pragma unroll
    for (int nt = 0; nt < 8; nt++) {
        const int c0 = nt * 8 + 2 * (lane & 3);
        *(float2*)&g_po[p * 4096 + irow_lo * 64 + c0] = make_float2(o[nt].x, o[nt].y);
        *(float2*)&g_po[p * 4096 + irow_hi * 64 + c0] = make_float2(o[nt].z, o[nt].w);
    }
    if ((lane & 3) == 0) {
        g_pm[p * 64 + irow_lo] = m_lo;
        g_pm[p * 64 + irow_hi] = m_hi;
        g_pl[p * 64 + irow_lo] = l_lo;
        g_pl[p * 64 + irow_hi] = l_hi;
    }
}

// ---------------------------------------------------------------------------
// Kernel 3: combine split-KV partials. grid = (NQT, BATCH), block = 256.
// ---------------------------------------------------------------------------
__global__ __launch_bounds__(256) void attn_reduce(float* __restrict__ out)
{
    const int qt = blockIdx.x;
    const int bb = blockIdx.y;
    const int nc = qt / 4 + 1;

    __shared__ float w[NCHUNK][64];
    __shared__ float invL[64];

    const int tid = threadIdx.x;
    const size_t pbase = (size_t)(bb * NQT + qt) * NCHUNK;

    if (tid < 64) {
        const int row = tid;
        float M = -INFINITY;
        for (int c = 0; c < nc; c++)
            M = fmaxf(M, g_pm[(pbase + c) * 64 + row]);
        float L = 0.f;
        for (int c = 0; c < nc; c++) {
            float wi = __expf(g_pm[(pbase + c) * 64 + row] - M);
            w[c][row] = wi;
            L += wi * g_pl[(pbase + c) * 64 + row];
        }
        invL[row] = 1.f / L;
    }
    __syncthreads();

#pragma unroll
    for (int i = 0; i < 4; i++) {
        int idx = tid + i * 256;
        int row = idx >> 4;
        int c4  = (idx & 15) * 4;
        float4 acc = make_float4(0.f, 0.f, 0.f, 0.f);
        for (int c = 0; c < nc; c++) {
            float4 v = *(const float4*)&g_po[(pbase + c) * 4096 + row * 64 + c4];
            float wi = w[c][row];
            acc.x = fmaf(wi, v.x, acc.x);
            acc.y = fmaf(wi, v.y, acc.y);
            acc.z = fmaf(wi, v.z, acc.z);
            acc.w = fmaf(wi, v.w, acc.w);
        }
        float inv = invL[row];
        acc.x *= inv; acc.y *= inv; acc.z *= inv; acc.w *= inv;
        *(float4*)&out[((size_t)bb * SEQ + qt * 64 + row) * HS + c4] = acc;
    }
}

// ---------------------------------------------------------------------------
extern "C" void kernel_launch(void* const* d_in, const int* in_sizes, int n_in,
                              void* d_out, int out_size)
{
    const float* xq  = (const float*)d_in[0];
    const float* xkv = (const float*)d_in[1];
    const float* Wq  = (const float*)d_in[2];
    const float* Wk  = (const float*)d_in[3];
    const float* Wv  = (const float*)d_in[4];
    float* out = (float*)d_out;

    const int attn_smem = 3 * 64 * AST * sizeof(float);   // 52224 B
    cudaFuncSetAttribute(attn_tc, cudaFuncAttributeMaxDynamicSharedMemorySize,
                         attn_smem);

    wsplit<<<192, 256>>>(Wq, Wk, Wv);
    qkv_tc<<<dim3(M_TOTAL / QBM, 3), 128>>>(xq, xkv);
    attn_tc<<<dim3(NQT, NCHUNK, BATCH), 128, attn_smem>>>();
    attn_reduce<<<dim3(NQT, BATCH), 256>>>(out);
}

// round 9
// speedup vs baseline: 2.9558x; 1.1389x over previous
#include <cuda_runtime.h>
#include <math.h>
#include <stdint.h>

#define BATCH 8
#define SEQ   2048
#define CDIM  1024
#define HS    64
#define M_TOTAL (BATCH * SEQ)   // 16384

#define NQT    (SEQ / 64)       // 32 query tiles per batch
#define NCHUNK 8                // 8 KV chunks of 256 keys (4 tiles of 64)

// Scratch (device globals: allowed).
__device__ float g_q[M_TOTAL * HS];
__device__ float g_k[M_TOTAL * HS];
__device__ float g_v[M_TOTAL * HS];
__device__ float g_po[(size_t)BATCH * NQT * NCHUNK * 64 * 64];
__device__ float g_pm[BATCH * NQT * NCHUNK * 64];
__device__ float g_pl[BATCH * NQT * NCHUNK * 64];
// Pre-split weights (tf32 hi/lo), layout [which][k][n]
__device__ float g_wh[3 * CDIM * HS];
__device__ float g_wl[3 * CDIM * HS];

// ---------------------------------------------------------------------------
// helpers
// ---------------------------------------------------------------------------
__device__ __forceinline__ float tf32r(float x) {
    uint32_t u;
    asm("cvt.rna.tf32.f32 %0, %1;" : "=r"(u) : "f"(x));
    return __uint_as_float(u);
}

__device__ __forceinline__ void mma_tf32(float4& d, const float* a, const float* b) {
    asm volatile(
        "mma.sync.aligned.m16n8k8.row.col.f32.tf32.tf32.f32 "
        "{%0,%1,%2,%3}, {%4,%5,%6,%7}, {%8,%9}, {%0,%1,%2,%3};"
        : "+f"(d.x), "+f"(d.y), "+f"(d.z), "+f"(d.w)
        : "r"(__float_as_uint(a[0])), "r"(__float_as_uint(a[1])),
          "r"(__float_as_uint(a[2])), "r"(__float_as_uint(a[3])),
          "r"(__float_as_uint(b[0])), "r"(__float_as_uint(b[1])));
}

__device__ __forceinline__ void cpa16(void* smem_dst, const void* gmem_src) {
    uint32_t s = (uint32_t)__cvta_generic_to_shared(smem_dst);
    asm volatile("cp.async.cg.shared.global [%0], [%1], 16;" :: "r"(s), "l"(gmem_src));
}
#define CP_COMMIT() asm volatile("cp.async.commit_group;")
#define CP_WAIT(n)  asm volatile("cp.async.wait_group %0;" :: "n"(n))

// ---------------------------------------------------------------------------
// Kernel 0: split W into tf32 hi/lo. 3*1024*64 = 196608 floats = 49152 float4.
// ---------------------------------------------------------------------------
__global__ __launch_bounds__(256) void wsplit(
    const float* __restrict__ Wq, const float* __restrict__ Wk,
    const float* __restrict__ Wv)
{
    const int idx = blockIdx.x * 256 + threadIdx.x;      // float4 id, 0..49151
    const float* W = (idx < 16384) ? Wq : (idx < 32768 ? Wk : Wv);
    const int local = (idx & 16383) * 4;
    float4 w = *(const float4*)&W[local];
    float4 h, l;
    h.x = tf32r(w.x); l.x = tf32r(w.x - h.x);
    h.y = tf32r(w.y); l.y = tf32r(w.y - h.y);
    h.z = tf32r(w.z); l.z = tf32r(w.z - h.z);
    h.w = tf32r(w.w); l.w = tf32r(w.w - h.w);
    *(float4*)&g_wh[idx * 4] = h;
    *(float4*)&g_wl[idx * 4] = l;
}

// ---------------------------------------------------------------------------
// Kernel 1: QKV projection, 3xTF32 mma, 256 threads (8 warps).
// Warp w owns rows w*16..w*16+15 of the 128-row tile, all 64 cols.
// ---------------------------------------------------------------------------
#define QBM 128
#define QBK 16
#define A_STR 20
#define B_STR 72
#define NKITER (CDIM / QBK)   // 64

__global__ __launch_bounds__(256) void qkv_tc(
    const float* __restrict__ xq, const float* __restrict__ xkv)
{
    const int which = blockIdx.y;                 // 0=Q, 1=K, 2=V
    const float* __restrict__ X  = (which == 0) ? xq : xkv;
    const float* __restrict__ WH = g_wh + which * CDIM * HS;
    const float* __restrict__ WL = g_wl + which * CDIM * HS;
    float* __restrict__ O = (which == 0) ? g_q : (which == 1 ? g_k : g_v);

    __shared__ __align__(16) float As[2][QBM][A_STR];
    __shared__ __align__(16) float Bh[2][QBK][B_STR];
    __shared__ __align__(16) float Bl[2][QBK][B_STR];

    const int tid  = threadIdx.x;
    const int warp = tid >> 5;
    const int lane = tid & 31;
    const int m0   = blockIdx.x * QBM;

    float4 acc[8];
#pragma unroll
    for (int nt = 0; nt < 8; nt++) acc[nt] = make_float4(0.f, 0.f, 0.f, 0.f);

    auto load_tile = [&](int it, int buf) {
        const int k0 = it * QBK;
#pragma unroll
        for (int i = 0; i < 2; i++) {
            int idx = tid + i * 256;       // 0..511
            int r   = idx >> 2;
            int c4  = (idx & 3) * 4;
            cpa16(&As[buf][r][c4], &X[(size_t)(m0 + r) * CDIM + k0 + c4]);
        }
        {
            int r  = tid >> 4;             // 0..15
            int c4 = (tid & 15) * 4;
            cpa16(&Bh[buf][r][c4], &WH[(size_t)(k0 + r) * HS + c4]);
            cpa16(&Bl[buf][r][c4], &WL[(size_t)(k0 + r) * HS + c4]);
        }
    };

    load_tile(0, 0);
    CP_COMMIT();

    const int arow = warp * 16 + (lane >> 2);
    const int kq   = lane & 3;
    const int bcol = lane >> 2;

    for (int it = 0; it < NKITER; it++) {
        const int buf = it & 1;
        if (it + 1 < NKITER) {
            load_tile(it + 1, buf ^ 1);
            CP_COMMIT();
            CP_WAIT(1);
        } else {
            CP_WAIT(0);
        }
        __syncthreads();

#pragma unroll
        for (int kk = 0; kk < 2; kk++) {
            const int ks = kk * 8;
            float ah[4], al[4];
            {
                float raw[4];
                raw[0] = As[buf][arow][ks + kq];
                raw[1] = As[buf][arow + 8][ks + kq];
                raw[2] = As[buf][arow][ks + kq + 4];
                raw[3] = As[buf][arow + 8][ks + kq + 4];
#pragma unroll
                for (int i = 0; i < 4; i++) {
                    ah[i] = tf32r(raw[i]);
                    al[i] = tf32r(raw[i] - ah[i]);
                }
            }
#pragma unroll
            for (int nt = 0; nt < 8; nt++) {
                float bh[2], bl[2];
                bh[0] = Bh[buf][ks + kq][nt * 8 + bcol];
                bh[1] = Bh[buf][ks + kq + 4][nt * 8 + bcol];
                bl[0] = Bl[buf][ks + kq][nt * 8 + bcol];
                bl[1] = Bl[buf][ks + kq + 4][nt * 8 + bcol];
                mma_tf32(acc[nt], ah, bh);
                mma_tf32(acc[nt], ah, bl);
                mma_tf32(acc[nt], al, bh);
            }
        }
        __syncthreads();
    }

    {
        const int row0 = m0 + warp * 16 + (lane >> 2);
#pragma unroll
        for (int nt = 0; nt < 8; nt++) {
            const int col = nt * 8 + 2 * (lane & 3);
            *(float2*)&O[(size_t)row0 * HS + col] =
                make_float2(acc[nt].x, acc[nt].y);
            *(float2*)&O[(size_t)(row0 + 8) * HS + col] =
                make_float2(acc[nt].z, acc[nt].w);
        }
    }
}

// ---------------------------------------------------------------------------
// Kernel 2: split-KV causal flash attention.
// S = QK^T single-pass tf32 (error ~1e-4 absolute on S, safe at 1e-3 gate);
// PV keeps 3-term split. grid = (NQT, NCHUNK, BATCH), block = 128 (4 warps).
// ---------------------------------------------------------------------------
#define AST 68

__global__ __launch_bounds__(128) void attn_tc(void)
{
    extern __shared__ float sm[];
    float* KVh = sm;                    // [64][AST]  (K hi, then V hi)
    float* KVl = sm + 64 * AST;         // [64][AST]  (V lo only)
    float* Ps  = sm + 2 * 64 * AST;     // [64][AST]

    const int qt  = blockIdx.x;
    const int cix = blockIdx.y;
    const int bb  = blockIdx.z;
    if (cix * 4 > qt) return;

    const int tid  = threadIdx.x;
    const int warp = tid >> 5;
    const int lane = tid & 31;
    const int r    = lane >> 2;        // 0..7 (fragment row / B col)
    const int kq   = lane & 3;         // quad k
    const float scale = 0.03125f;      // 1024^-0.5

    // ---- Q fragments hoisted (single tf32; no lo part needed)
    float qh[8][4];
    {
        const float* Qg = g_q + ((size_t)bb * SEQ + qt * 64 + warp * 16) * HS;
#pragma unroll
        for (int ks = 0; ks < 8; ks++) {
            qh[ks][0] = tf32r(Qg[r * HS + 8 * ks + kq]);
            qh[ks][1] = tf32r(Qg[(r + 8) * HS + 8 * ks + kq]);
            qh[ks][2] = tf32r(Qg[r * HS + 8 * ks + kq + 4]);
            qh[ks][3] = tf32r(Qg[(r + 8) * HS + 8 * ks + kq + 4]);
        }
    }

    float4 o[8];
#pragma unroll
    for (int nt = 0; nt < 8; nt++) o[nt] = make_float4(0.f, 0.f, 0.f, 0.f);
    float m_lo = -INFINITY, m_hi = -INFINITY, l_lo = 0.f, l_hi = 0.f;

    const int kt_begin = cix * 4;
    const int kt_end   = (cix * 4 + 3 < qt) ? (cix * 4 + 3) : qt;

    for (int kt = kt_begin; kt <= kt_end; kt++) {
        const float* Kg = g_k + ((size_t)bb * SEQ + kt * 64) * HS;
        const float* Vg = g_v + ((size_t)bb * SEQ + kt * 64) * HS;

        __syncthreads();   // prev-iter V reads (PV) done before K overwrite

        // ---- K load (tf32 hi only), permuted: h -> (h&~7)|((h&3)<<1)|((h>>2)&1)
#pragma unroll
        for (int i = 0; i < 8; i++) {
            int idx = tid + i * 128;   // float4 id 0..1023
            int row = idx >> 4;
            int c4  = (idx & 15) * 4;
            float4 v = *(const float4*)&Kg[row * HS + c4];
            float vals[4] = {v.x, v.y, v.z, v.w};
#pragma unroll
            for (int j = 0; j < 4; j++) {
                int h = c4 + j;
                int p = (h & ~7) | ((h & 3) << 1) | ((h >> 2) & 1);
                KVh[row * AST + p] = tf32r(vals[j]);
            }
        }
        __syncthreads();

        // ---- S = Q K^T (single pass)
        float4 s[8];
#pragma unroll
        for (int nt = 0; nt < 8; nt++) s[nt] = make_float4(0.f, 0.f, 0.f, 0.f);

#pragma unroll
        for (int ks = 0; ks < 8; ks++) {
#pragma unroll
            for (int nt = 0; nt < 8; nt++) {
                const int jrow = nt * 8 + r;
                float2 bh = *(const float2*)&KVh[jrow * AST + 8 * ks + 2 * kq];
                mma_tf32(s[nt], qh[ks], (const float*)&bh);
            }
        }

        // ---- scale + causal mask
        const bool diag = (kt == qt);
        const int irow_lo = warp * 16 + r;
        const int irow_hi = irow_lo + 8;
#pragma unroll
        for (int nt = 0; nt < 8; nt++) {
            const int c0 = nt * 8 + 2 * kq;
            s[nt].x *= scale; s[nt].y *= scale;
            s[nt].z *= scale; s[nt].w *= scale;
            if (diag) {
                if (c0     > irow_lo) s[nt].x = -INFINITY;
                if (c0 + 1 > irow_lo) s[nt].y = -INFINITY;
                if (c0     > irow_hi) s[nt].z = -INFINITY;
                if (c0 + 1 > irow_hi) s[nt].w = -INFINITY;
            }
        }

        // ---- row max (local 16 + shuffle over 4-lane group)
        float rmax_lo = -INFINITY, rmax_hi = -INFINITY;
#pragma unroll
        for (int nt = 0; nt < 8; nt++) {
            rmax_lo = fmaxf(rmax_lo, fmaxf(s[nt].x, s[nt].y));
            rmax_hi = fmaxf(rmax_hi, fmaxf(s[nt].z, s[nt].w));
        }
        rmax_lo = fmaxf(rmax_lo, __shfl_xor_sync(0xffffffffu, rmax_lo, 1));
        rmax_lo = fmaxf(rmax_lo, __shfl_xor_sync(0xffffffffu, rmax_lo, 2));
        rmax_hi = fmaxf(rmax_hi, __shfl_xor_sync(0xffffffffu, rmax_hi, 1));
        rmax_hi = fmaxf(rmax_hi, __shfl_xor_sync(0xffffffffu, rmax_hi, 2));

        float mn_lo = fmaxf(m_lo, rmax_lo);
        float mn_hi = fmaxf(m_hi, rmax_hi);
        float alpha_lo = __expf(m_lo - mn_lo);
        float alpha_hi = __expf(m_hi - mn_hi);
        m_lo = mn_lo; m_hi = mn_hi;

        // ---- p = exp(s - m), write raw P to smem, row sums
        float rsum_lo = 0.f, rsum_hi = 0.f;
#pragma unroll
        for (int nt = 0; nt < 8; nt++) {
            const int c0 = nt * 8 + 2 * kq;
            float px = __expf(s[nt].x - m_lo);
            float py = __expf(s[nt].y - m_lo);
            float pz = __expf(s[nt].z - m_hi);
            float pw = __expf(s[nt].w - m_hi);
            rsum_lo += px + py;
            rsum_hi += pz + pw;
            *(float2*)&Ps[irow_lo * AST + c0] = make_float2(px, py);
            *(float2*)&Ps[irow_hi * AST + c0] = make_float2(pz, pw);
        }
        rsum_lo += __shfl_xor_sync(0xffffffffu, rsum_lo, 1);
        rsum_lo += __shfl_xor_sync(0xffffffffu, rsum_lo, 2);
        rsum_hi += __shfl_xor_sync(0xffffffffu, rsum_hi, 1);
        rsum_hi += __shfl_xor_sync(0xffffffffu, rsum_hi, 2);

        l_lo = l_lo * alpha_lo + rsum_lo;
        l_hi = l_hi * alpha_hi + rsum_hi;
#pragma unroll
        for (int nt = 0; nt < 8; nt++) {
            o[nt].x *= alpha_lo; o[nt].y *= alpha_lo;
            o[nt].z *= alpha_hi; o[nt].w *= alpha_hi;
        }

        __syncthreads();   // all warps done reading K before V overwrite

        // ---- V load + tf32 split (natural layout [j][col])
#pragma unroll
        for (int i = 0; i < 8; i++) {
            int idx = tid + i * 128;
            int row = idx >> 4;
            int c4  = (idx & 15) * 4;
            float4 v = *(const float4*)&Vg[row * HS + c4];
            float4 h4, l4;
            h4.x = tf32r(v.x); l4.x = tf32r(v.x - h4.x);
            h4.y = tf32r(v.y); l4.y = tf32r(v.y - h4.y);
            h4.z = tf32r(v.z); l4.z = tf32r(v.z - h4.z);
            h4.w = tf32r(v.w); l4.w = tf32r(v.w - h4.w);
            *(float4*)&KVh[row * AST + c4] = h4;
            *(float4*)&KVl[row * AST + c4] = l4;
        }
        __syncthreads();

        // ---- O += P V (3-term; P raw split at read, same-warp rows)
#pragma unroll
        for (int ks = 0; ks < 8; ks++) {
            float raw[4];
            raw[0] = Ps[irow_lo * AST + 8 * ks + kq];
            raw[1] = Ps[irow_hi * AST + 8 * ks + kq];
            raw[2] = Ps[irow_lo * AST + 8 * ks + kq + 4];
            raw[3] = Ps[irow_hi * AST + 8 * ks + kq + 4];
            float ah[4], al[4];
#pragma unroll
            for (int i = 0; i < 4; i++) {
                ah[i] = tf32r(raw[i]);
                al[i] = tf32r(raw[i] - ah[i]);
            }
#pragma unroll
            for (int nt = 0; nt < 8; nt++) {
                float bh[2], bl[2];
                bh[0] = KVh[(8 * ks + kq) * AST + nt * 8 + r];
                bh[1] = KVh[(8 * ks + kq + 4) * AST + nt * 8 + r];
                bl[0] = KVl[(8 * ks + kq) * AST + nt * 8 + r];
                bl[1] = KVl[(8 * ks + kq + 4) * AST + nt * 8 + r];
                mma_tf32(o[nt], ah, bh);
                mma_tf32(o[nt], ah, bl);
                mma_tf32(o[nt], al, bh);
            }
        }
    }

    // ---- store partials (unnormalized) + m, l
    const size_t p = ((size_t)(bb * NQT + qt) * NCHUNK + cix);
    const int irow_lo = warp * 16 + (lane >> 2);
    const int irow_hi = irow_lo + 8;
#pragma unroll
    for (int nt = 0; nt < 8; nt++) {
        const int c0 = nt * 8 + 2 * (lane & 3);
        *(float2*)&g_po[p * 4096 + irow_lo * 64 + c0] = make_float2(o[nt].x, o[nt].y);
        *(float2*)&g_po[p * 4096 + irow_hi * 64 + c0] = make_float2(o[nt].z, o[nt].w);
    }
    if ((lane & 3) == 0) {
        g_pm[p * 64 + irow_lo] = m_lo;
        g_pm[p * 64 + irow_hi] = m_hi;
        g_pl[p * 64 + irow_lo] = l_lo;
        g_pl[p * 64 + irow_hi] = l_hi;
    }
}

// ---------------------------------------------------------------------------
// Kernel 3: combine split-KV partials.
// grid = (NQT, BATCH, 4), block = 128; each CTA handles 16 rows.
// ---------------------------------------------------------------------------
__global__ __launch_bounds__(128) void attn_reduce(float* __restrict__ out)
{
    const int qt = blockIdx.x;
    const int bb = blockIdx.y;
    const int rz = blockIdx.z;             // row group: rows rz*16..+15
    const int nc = qt / 4 + 1;

    __shared__ float w[NCHUNK][16];
    __shared__ float invL[16];

    const int tid = threadIdx.x;
    const size_t pbase = (size_t)(bb * NQT + qt) * NCHUNK;

    if (tid < 16) {
        const int row = rz * 16 + tid;
        float M = -INFINITY;
        for (int c = 0; c < nc; c++)
            M = fmaxf(M, g_pm[(pbase + c) * 64 + row]);
        float L = 0.f;
        for (int c = 0; c < nc; c++) {
            float wi = __expf(g_pm[(pbase + c) * 64 + row] - M);
            w[c][tid] = wi;
            L += wi * g_pl[(pbase + c) * 64 + row];
        }
        invL[tid] = 1.f / L;
    }
    __syncthreads();

#pragma unroll
    for (int i = 0; i < 2; i++) {
        int idx = tid + i * 128;           // 0..255 float4 slots
        int rl  = idx >> 4;                // 0..15
        int c4  = (idx & 15) * 4;
        const int row = rz * 16 + rl;
        float4 acc = make_float4(0.f, 0.f, 0.f, 0.f);
        for (int c = 0; c < nc; c++) {
            float4 v = *(const float4*)&g_po[(pbase + c) * 4096 + row * 64 + c4];
            float wi = w[c][rl];
            acc.x = fmaf(wi, v.x, acc.x);
            acc.y = fmaf(wi, v.y, acc.y);
            acc.z = fmaf(wi, v.z, acc.z);
            acc.w = fmaf(wi, v.w, acc.w);
        }
        float inv = invL[rl];
        acc.x *= inv; acc.y *= inv; acc.z *= inv; acc.w *= inv;
        *(float4*)&out[((size_t)bb * SEQ + qt * 64 + row) * HS + c4] = acc;
    }
}

// ---------------------------------------------------------------------------
extern "C" void kernel_launch(void* const* d_in, const int* in_sizes, int n_in,
                              void* d_out, int out_size)
{
    const float* xq  = (const float*)d_in[0];
    const float* xkv = (const float*)d_in[1];
    const float* Wq  = (const float*)d_in[2];
    const float* Wk  = (const float*)d_in[3];
    const float* Wv  = (const float*)d_in[4];
    float* out = (float*)d_out;

    const int attn_smem = 3 * 64 * AST * sizeof(float);   // 52224 B
    cudaFuncSetAttribute(attn_tc, cudaFuncAttributeMaxDynamicSharedMemorySize,
                         attn_smem);

    wsplit<<<192, 256>>>(Wq, Wk, Wv);
    qkv_tc<<<dim3(M_TOTAL / QBM, 3), 256>>>(xq, xkv);
    attn_tc<<<dim3(NQT, NCHUNK, BATCH), 128, attn_smem>>>();
    attn_reduce<<<dim3(NQT, BATCH, 4), 128>>>(out);
}

// round 11
// speedup vs baseline: 3.1938x; 1.0805x over previous
#include <cuda_runtime.h>
#include <math.h>
#include <stdint.h>

#define BATCH 8
#define SEQ   2048
#define CDIM  1024
#define HS    64
#define M_TOTAL (BATCH * SEQ)   // 16384

#define NQT    (SEQ / 64)       // 32 query tiles per batch
#define NCHUNK 8                // 8 KV chunks of 256 keys (4 tiles of 64)

// Scratch (device globals: allowed).
__device__ float g_q[M_TOTAL * HS];
__device__ float g_k[M_TOTAL * HS];
__device__ float g_v[M_TOTAL * HS];
__device__ float g_po[(size_t)BATCH * NQT * NCHUNK * 64 * 64];
__device__ float g_pm[BATCH * NQT * NCHUNK * 64];
__device__ float g_pl[BATCH * NQT * NCHUNK * 64];
// Pre-split weights (tf32 hi/lo), layout [which][k][n]
__device__ float g_wh[3 * CDIM * HS];
__device__ float g_wl[3 * CDIM * HS];

// ---------------------------------------------------------------------------
// helpers
// ---------------------------------------------------------------------------
__device__ __forceinline__ float tf32r(float x) {
    uint32_t u;
    asm("cvt.rna.tf32.f32 %0, %1;" : "=r"(u) : "f"(x));
    return __uint_as_float(u);
}

__device__ __forceinline__ void mma_tf32(float4& d, const float* a, const float* b) {
    asm volatile(
        "mma.sync.aligned.m16n8k8.row.col.f32.tf32.tf32.f32 "
        "{%0,%1,%2,%3}, {%4,%5,%6,%7}, {%8,%9}, {%0,%1,%2,%3};"
        : "+f"(d.x), "+f"(d.y), "+f"(d.z), "+f"(d.w)
        : "r"(__float_as_uint(a[0])), "r"(__float_as_uint(a[1])),
          "r"(__float_as_uint(a[2])), "r"(__float_as_uint(a[3])),
          "r"(__float_as_uint(b[0])), "r"(__float_as_uint(b[1])));
}

__device__ __forceinline__ void cpa16(void* smem_dst, const void* gmem_src) {
    uint32_t s = (uint32_t)__cvta_generic_to_shared(smem_dst);
    asm volatile("cp.async.cg.shared.global [%0], [%1], 16;" :: "r"(s), "l"(gmem_src));
}
#define CP_COMMIT() asm volatile("cp.async.commit_group;")
#define CP_WAIT(n)  asm volatile("cp.async.wait_group %0;" :: "n"(n))

// ---------------------------------------------------------------------------
// Kernel 0: split W into tf32 hi/lo. 3*1024*64 = 196608 floats = 49152 float4.
// ---------------------------------------------------------------------------
__global__ __launch_bounds__(256) void wsplit(
    const float* __restrict__ Wq, const float* __restrict__ Wk,
    const float* __restrict__ Wv)
{
    const int idx = blockIdx.x * 256 + threadIdx.x;      // float4 id, 0..49151
    const float* W = (idx < 16384) ? Wq : (idx < 32768 ? Wk : Wv);
    const int local = (idx & 16383) * 4;
    float4 w = *(const float4*)&W[local];
    float4 h, l;
    h.x = tf32r(w.x); l.x = tf32r(w.x - h.x);
    h.y = tf32r(w.y); l.y = tf32r(w.y - h.y);
    h.z = tf32r(w.z); l.z = tf32r(w.z - h.z);
    h.w = tf32r(w.w); l.w = tf32r(w.w - h.w);
    *(float4*)&g_wh[idx * 4] = h;
    *(float4*)&g_wl[idx * 4] = l;
}

// ---------------------------------------------------------------------------
// Kernel 1: QKV projection, 3xTF32 mma, 256 threads (8 warps).
// Warp w owns rows w*16..w*16+15 of the 128-row tile, all 64 cols.
// ---------------------------------------------------------------------------
#define QBM 128
#define QBK 16
#define A_STR 20
#define B_STR 72
#define NKITER (CDIM / QBK)   // 64

__global__ __launch_bounds__(256) void qkv_tc(
    const float* __restrict__ xq, const float* __restrict__ xkv)
{
    const int which = blockIdx.y;                 // 0=Q, 1=K, 2=V
    const float* __restrict__ X  = (which == 0) ? xq : xkv;
    const float* __restrict__ WH = g_wh + which * CDIM * HS;
    const float* __restrict__ WL = g_wl + which * CDIM * HS;
    float* __restrict__ O = (which == 0) ? g_q : (which == 1 ? g_k : g_v);

    __shared__ __align__(16) float As[2][QBM][A_STR];
    __shared__ __align__(16) float Bh[2][QBK][B_STR];
    __shared__ __align__(16) float Bl[2][QBK][B_STR];

    const int tid  = threadIdx.x;
    const int warp = tid >> 5;
    const int lane = tid & 31;
    const int m0   = blockIdx.x * QBM;

    float4 acc[8];
#pragma unroll
    for (int nt = 0; nt < 8; nt++) acc[nt] = make_float4(0.f, 0.f, 0.f, 0.f);

    auto load_tile = [&](int it, int buf) {
        const int k0 = it * QBK;
#pragma unroll
        for (int i = 0; i < 2; i++) {
            int idx = tid + i * 256;       // 0..511
            int r   = idx >> 2;
            int c4  = (idx & 3) * 4;
            cpa16(&As[buf][r][c4], &X[(size_t)(m0 + r) * CDIM + k0 + c4]);
        }
        {
            int r  = tid >> 4;             // 0..15
            int c4 = (tid & 15) * 4;
            cpa16(&Bh[buf][r][c4], &WH[(size_t)(k0 + r) * HS + c4]);
            cpa16(&Bl[buf][r][c4], &WL[(size_t)(k0 + r) * HS + c4]);
        }
    };

    load_tile(0, 0);
    CP_COMMIT();

    const int arow = warp * 16 + (lane >> 2);
    const int kq   = lane & 3;
    const int bcol = lane >> 2;

    for (int it = 0; it < NKITER; it++) {
        const int buf = it & 1;
        if (it + 1 < NKITER) {
            load_tile(it + 1, buf ^ 1);
            CP_COMMIT();
            CP_WAIT(1);
        } else {
            CP_WAIT(0);
        }
        __syncthreads();

#pragma unroll
        for (int kk = 0; kk < 2; kk++) {
            const int ks = kk * 8;
            float ah[4], al[4];
            {
                float raw[4];
                raw[0] = As[buf][arow][ks + kq];
                raw[1] = As[buf][arow + 8][ks + kq];
                raw[2] = As[buf][arow][ks + kq + 4];
                raw[3] = As[buf][arow + 8][ks + kq + 4];
#pragma unroll
                for (int i = 0; i < 4; i++) {
                    ah[i] = tf32r(raw[i]);
                    al[i] = tf32r(raw[i] - ah[i]);
                }
            }
#pragma unroll
            for (int nt = 0; nt < 8; nt++) {
                float bh[2], bl[2];
                bh[0] = Bh[buf][ks + kq][nt * 8 + bcol];
                bh[1] = Bh[buf][ks + kq + 4][nt * 8 + bcol];
                bl[0] = Bl[buf][ks + kq][nt * 8 + bcol];
                bl[1] = Bl[buf][ks + kq + 4][nt * 8 + bcol];
                mma_tf32(acc[nt], ah, bh);
                mma_tf32(acc[nt], ah, bl);
                mma_tf32(acc[nt], al, bh);
            }
        }
        __syncthreads();
    }

    {
        const int row0 = m0 + warp * 16 + (lane >> 2);
#pragma unroll
        for (int nt = 0; nt < 8; nt++) {
            const int col = nt * 8 + 2 * (lane & 3);
            *(float2*)&O[(size_t)row0 * HS + col] =
                make_float2(acc[nt].x, acc[nt].y);
            *(float2*)&O[(size_t)(row0 + 8) * HS + col] =
                make_float2(acc[nt].z, acc[nt].w);
        }
    }
}

// ---------------------------------------------------------------------------
// Kernel 2: split-KV causal flash attention.
// S = QK^T single-pass tf32; PV = (Ph + Pl) x tf32(V) (2 mmas, V single-pass).
// smem down to 2 buffers (KVh + Ps) = 34.8 KB -> 6 CTAs/SM.
// grid = (NQT, NCHUNK, BATCH), block = 128 (4 warps).
// ---------------------------------------------------------------------------
#define AST 68

__global__ __launch_bounds__(128) void attn_tc(void)
{
    extern __shared__ float sm[];
    float* KVh = sm;                    // [64][AST]  (K hi, then V hi)
    float* Ps  = sm + 64 * AST;         // [64][AST]

    const int qt  = blockIdx.x;
    const int cix = blockIdx.y;
    const int bb  = blockIdx.z;
    if (cix * 4 > qt) return;

    const int tid  = threadIdx.x;
    const int warp = tid >> 5;
    const int lane = tid & 31;
    const int r    = lane >> 2;        // 0..7 (fragment row / B col)
    const int kq   = lane & 3;         // quad k
    const float scale = 0.03125f;      // 1024^-0.5

    // ---- Q fragments hoisted (single tf32; no lo part needed)
    float qh[8][4];
    {
        const float* Qg = g_q + ((size_t)bb * SEQ + qt * 64 + warp * 16) * HS;
#pragma unroll
        for (int ks = 0; ks < 8; ks++) {
            qh[ks][0] = tf32r(Qg[r * HS + 8 * ks + kq]);
            qh[ks][1] = tf32r(Qg[(r + 8) * HS + 8 * ks + kq]);
            qh[ks][2] = tf32r(Qg[r * HS + 8 * ks + kq + 4]);
            qh[ks][3] = tf32r(Qg[(r + 8) * HS + 8 * ks + kq + 4]);
        }
    }

    float4 o[8];
#pragma unroll
    for (int nt = 0; nt < 8; nt++) o[nt] = make_float4(0.f, 0.f, 0.f, 0.f);
    float m_lo = -INFINITY, m_hi = -INFINITY, l_lo = 0.f, l_hi = 0.f;

    const int kt_begin = cix * 4;
    const int kt_end   = (cix * 4 + 3 < qt) ? (cix * 4 + 3) : qt;

    for (int kt = kt_begin; kt <= kt_end; kt++) {
        const float* Kg = g_k + ((size_t)bb * SEQ + kt * 64) * HS;
        const float* Vg = g_v + ((size_t)bb * SEQ + kt * 64) * HS;

        __syncthreads();   // prev-iter V reads (PV) done before K overwrite

        // ---- K load (tf32 hi only), permuted: h -> (h&~7)|((h&3)<<1)|((h>>2)&1)
#pragma unroll
        for (int i = 0; i < 8; i++) {
            int idx = tid + i * 128;   // float4 id 0..1023
            int row = idx >> 4;
            int c4  = (idx & 15) * 4;
            float4 v = *(const float4*)&Kg[row * HS + c4];
            float vals[4] = {v.x, v.y, v.z, v.w};
#pragma unroll
            for (int j = 0; j < 4; j++) {
                int h = c4 + j;
                int p = (h & ~7) | ((h & 3) << 1) | ((h >> 2) & 1);
                KVh[row * AST + p] = tf32r(vals[j]);
            }
        }
        __syncthreads();

        // ---- S = Q K^T (single pass)
        float4 s[8];
#pragma unroll
        for (int nt = 0; nt < 8; nt++) s[nt] = make_float4(0.f, 0.f, 0.f, 0.f);

#pragma unroll
        for (int ks = 0; ks < 8; ks++) {
#pragma unroll
            for (int nt = 0; nt < 8; nt++) {
                const int jrow = nt * 8 + r;
                float2 bh = *(const float2*)&KVh[jrow * AST + 8 * ks + 2 * kq];
                mma_tf32(s[nt], qh[ks], (const float*)&bh);
            }
        }

        // ---- scale + causal mask
        const bool diag = (kt == qt);
        const int irow_lo = warp * 16 + r;
        const int irow_hi = irow_lo + 8;
#pragma unroll
        for (int nt = 0; nt < 8; nt++) {
            const int c0 = nt * 8 + 2 * kq;
            s[nt].x *= scale; s[nt].y *= scale;
            s[nt].z *= scale; s[nt].w *= scale;
            if (diag) {
                if (c0     > irow_lo) s[nt].x = -INFINITY;
                if (c0 + 1 > irow_lo) s[nt].y = -INFINITY;
                if (c0     > irow_hi) s[nt].z = -INFINITY;
                if (c0 + 1 > irow_hi) s[nt].w = -INFINITY;
            }
        }

        // ---- row max (local 16 + shuffle over 4-lane group)
        float rmax_lo = -INFINITY, rmax_hi = -INFINITY;
#pragma unroll
        for (int nt = 0; nt < 8; nt++) {
            rmax_lo = fmaxf(rmax_lo, fmaxf(s[nt].x, s[nt].y));
            rmax_hi = fmaxf(rmax_hi, fmaxf(s[nt].z, s[nt].w));
        }
        rmax_lo = fmaxf(rmax_lo, __shfl_xor_sync(0xffffffffu, rmax_lo, 1));
        rmax_lo = fmaxf(rmax_lo, __shfl_xor_sync(0xffffffffu, rmax_lo, 2));
        rmax_hi = fmaxf(rmax_hi, __shfl_xor_sync(0xffffffffu, rmax_hi, 1));
        rmax_hi = fmaxf(rmax_hi, __shfl_xor_sync(0xffffffffu, rmax_hi, 2));

        float mn_lo = fmaxf(m_lo, rmax_lo);
        float mn_hi = fmaxf(m_hi, rmax_hi);
        float alpha_lo = __expf(m_lo - mn_lo);
        float alpha_hi = __expf(m_hi - mn_hi);
        m_lo = mn_lo; m_hi = mn_hi;

        // ---- p = exp(s - m), write raw P to smem, row sums
        float rsum_lo = 0.f, rsum_hi = 0.f;
#pragma unroll
        for (int nt = 0; nt < 8; nt++) {
            const int c0 = nt * 8 + 2 * kq;
            float px = __expf(s[nt].x - m_lo);
            float py = __expf(s[nt].y - m_lo);
            float pz = __expf(s[nt].z - m_hi);
            float pw = __expf(s[nt].w - m_hi);
            rsum_lo += px + py;
            rsum_hi += pz + pw;
            *(float2*)&Ps[irow_lo * AST + c0] = make_float2(px, py);
            *(float2*)&Ps[irow_hi * AST + c0] = make_float2(pz, pw);
        }
        rsum_lo += __shfl_xor_sync(0xffffffffu, rsum_lo, 1);
        rsum_lo += __shfl_xor_sync(0xffffffffu, rsum_lo, 2);
        rsum_hi += __shfl_xor_sync(0xffffffffu, rsum_hi, 1);
        rsum_hi += __shfl_xor_sync(0xffffffffu, rsum_hi, 2);

        l_lo = l_lo * alpha_lo + rsum_lo;
        l_hi = l_hi * alpha_hi + rsum_hi;
#pragma unroll
        for (int nt = 0; nt < 8; nt++) {
            o[nt].x *= alpha_lo; o[nt].y *= alpha_lo;
            o[nt].z *= alpha_hi; o[nt].w *= alpha_hi;
        }

        __syncthreads();   // all warps done reading K before V overwrite

        // ---- V load, single-pass tf32 (natural layout [j][col])
#pragma unroll
        for (int i = 0; i < 8; i++) {
            int idx = tid + i * 128;
            int row = idx >> 4;
            int c4  = (idx & 15) * 4;
            float4 v = *(const float4*)&Vg[row * HS + c4];
            float4 h4;
            h4.x = tf32r(v.x);
            h4.y = tf32r(v.y);
            h4.z = tf32r(v.z);
            h4.w = tf32r(v.w);
            *(float4*)&KVh[row * AST + c4] = h4;
        }
        __syncthreads();

        // ---- O += P V (P split hi/lo for exactness, V single-pass: 2 mmas)
#pragma unroll
        for (int ks = 0; ks < 8; ks++) {
            float raw[4];
            raw[0] = Ps[irow_lo * AST + 8 * ks + kq];
            raw[1] = Ps[irow_hi * AST + 8 * ks + kq];
            raw[2] = Ps[irow_lo * AST + 8 * ks + kq + 4];
            raw[3] = Ps[irow_hi * AST + 8 * ks + kq + 4];
            float ah[4], al[4];
#pragma unroll
            for (int i = 0; i < 4; i++) {
                ah[i] = tf32r(raw[i]);
                al[i] = tf32r(raw[i] - ah[i]);
            }
#pragma unroll
            for (int nt = 0; nt < 8; nt++) {
                float bh[2];
                bh[0] = KVh[(8 * ks + kq) * AST + nt * 8 + r];
                bh[1] = KVh[(8 * ks + kq + 4) * AST + nt * 8 + r];
                mma_tf32(o[nt], ah, bh);
                mma_tf32(o[nt], al, bh);
            }
        }
    }

    // ---- store partials (unnormalized) + m, l
    const size_t p = ((size_t)(bb * NQT + qt) * NCHUNK + cix);
    const int irow_lo = warp * 16 + (lane >> 2);
    const int irow_hi = irow_lo + 8;
#pragma unroll
    for (int nt = 0; nt < 8; nt++) {
        const int c0 = nt * 8 + 2 * (lane & 3);
        *(float2*)&g_po[p * 4096 + irow_lo * 64 + c0] = make_float2(o[nt].x, o[nt].y);
        *(float2*)&g_po[p * 4096 + irow_hi * 64 + c0] = make_float2(o[nt].z, o[nt].w);
    }
    if ((lane & 3) == 0) {
        g_pm[p * 64 + irow_lo] = m_lo;
        g_pm[p * 64 + irow_hi] = m_hi;
        g_pl[p * 64 + irow_lo] = l_lo;
        g_pl[p * 64 + irow_hi] = l_hi;
    }
}

// ---------------------------------------------------------------------------
// Kernel 3: combine split-KV partials.
// grid = (NQT, BATCH, 4), block = 128; each CTA handles 16 rows.
// ---------------------------------------------------------------------------
__global__ __launch_bounds__(128) void attn_reduce(float* __restrict__ out)
{
    const int qt = blockIdx.x;
    const int bb = blockIdx.y;
    const int rz = blockIdx.z;             // row group: rows rz*16..+15
    const int nc = qt / 4 + 1;

    __shared__ float w[NCHUNK][16];
    __shared__ float invL[16];

    const int tid = threadIdx.x;
    const size_t pbase = (size_t)(bb * NQT + qt) * NCHUNK;

    if (tid < 16) {
        const int row = rz * 16 + tid;
        float M = -INFINITY;
        for (int c = 0; c < nc; c++)
            M = fmaxf(M, g_pm[(pbase + c) * 64 + row]);
        float L = 0.f;
        for (int c = 0; c < nc; c++) {
            float wi = __expf(g_pm[(pbase + c) * 64 + row] - M);
            w[c][tid] = wi;
            L += wi * g_pl[(pbase + c) * 64 + row];
        }
        invL[tid] = 1.f / L;
    }
    __syncthreads();

#pragma unroll
    for (int i = 0; i < 2; i++) {
        int idx = tid + i * 128;           // 0..255 float4 slots
        int rl  = idx >> 4;                // 0..15
        int c4  = (idx & 15) * 4;
        const int row = rz * 16 + rl;
        float4 acc = make_float4(0.f, 0.f, 0.f, 0.f);
        for (int c = 0; c < nc; c++) {
            float4 v = *(const float4*)&g_po[(pbase + c) * 4096 + row * 64 + c4];
            float wi = w[c][rl];
            acc.x = fmaf(wi, v.x, acc.x);
            acc.y = fmaf(wi, v.y, acc.y);
            acc.z = fmaf(wi, v.z, acc.z);
            acc.w = fmaf(wi, v.w, acc.w);
        }
        float inv = invL[rl];
        acc.x *= inv; acc.y *= inv; acc.z *= inv; acc.w *= inv;
        *(float4*)&out[((size_t)bb * SEQ + qt * 64 + row) * HS + c4] = acc;
    }
}

// ---------------------------------------------------------------------------
extern "C" void kernel_launch(void* const* d_in, const int* in_sizes, int n_in,
                              void* d_out, int out_size)
{
    const float* xq  = (const float*)d_in[0];
    const float* xkv = (const float*)d_in[1];
    const float* Wq  = (const float*)d_in[2];
    const float* Wk  = (const float*)d_in[3];
    const float* Wv  = (const float*)d_in[4];
    float* out = (float*)d_out;

    const int attn_smem = 2 * 64 * AST * sizeof(float);   // 34816 B
    cudaFuncSetAttribute(attn_tc, cudaFuncAttributeMaxDynamicSharedMemorySize,
                         attn_smem);

    wsplit<<<192, 256>>>(Wq, Wk, Wv);
    qkv_tc<<<dim3(M_TOTAL / QBM, 3), 256>>>(xq, xkv);
    attn_tc<<<dim3(NQT, NCHUNK, BATCH), 128, attn_smem>>>();
    attn_reduce<<<dim3(NQT, BATCH, 4), 128>>>(out);
}

// round 12
// speedup vs baseline: 3.6991x; 1.1582x over previous
#include <cuda_runtime.h>
#include <math.h>
#include <stdint.h>

#define BATCH 8
#define SEQ   2048
#define CDIM  1024
#define HS    64
#define M_TOTAL (BATCH * SEQ)   // 16384

#define NQT    (SEQ / 64)       // 32 query tiles per batch
#define NCHUNK 8                // 8 KV chunks of 256 keys (4 tiles of 64)

// Scratch (device globals: allowed).
__device__ float g_q[M_TOTAL * HS];
__device__ float g_k[M_TOTAL * HS];
__device__ float g_v[M_TOTAL * HS];
__device__ float g_po[(size_t)BATCH * NQT * NCHUNK * 64 * 64];
__device__ float g_pm[BATCH * NQT * NCHUNK * 64];
__device__ float g_pl[BATCH * NQT * NCHUNK * 64];
// Pre-split weights (tf32 hi/lo), layout [which][k][n]
__device__ float g_wh[3 * CDIM * HS];
__device__ float g_wl[3 * CDIM * HS];

// ---------------------------------------------------------------------------
// helpers
// ---------------------------------------------------------------------------
__device__ __forceinline__ float tf32r(float x) {
    uint32_t u;
    asm("cvt.rna.tf32.f32 %0, %1;" : "=r"(u) : "f"(x));
    return __uint_as_float(u);
}

__device__ __forceinline__ void mma_tf32(float4& d, const float* a, const float* b) {
    asm volatile(
        "mma.sync.aligned.m16n8k8.row.col.f32.tf32.tf32.f32 "
        "{%0,%1,%2,%3}, {%4,%5,%6,%7}, {%8,%9}, {%0,%1,%2,%3};"
        : "+f"(d.x), "+f"(d.y), "+f"(d.z), "+f"(d.w)
        : "r"(__float_as_uint(a[0])), "r"(__float_as_uint(a[1])),
          "r"(__float_as_uint(a[2])), "r"(__float_as_uint(a[3])),
          "r"(__float_as_uint(b[0])), "r"(__float_as_uint(b[1])));
}

__device__ __forceinline__ void cpa16(void* smem_dst, const void* gmem_src) {
    uint32_t s = (uint32_t)__cvta_generic_to_shared(smem_dst);
    asm volatile("cp.async.cg.shared.global [%0], [%1], 16;" :: "r"(s), "l"(gmem_src));
}
#define CP_COMMIT() asm volatile("cp.async.commit_group;")
#define CP_WAIT(n)  asm volatile("cp.async.wait_group %0;" :: "n"(n))

// ---------------------------------------------------------------------------
// Kernel 0: split W into tf32 hi/lo. 3*1024*64 = 196608 floats = 49152 float4.
// ---------------------------------------------------------------------------
__global__ __launch_bounds__(256) void wsplit(
    const float* __restrict__ Wq, const float* __restrict__ Wk,
    const float* __restrict__ Wv)
{
    const int idx = blockIdx.x * 256 + threadIdx.x;      // float4 id, 0..49151
    const float* W = (idx < 16384) ? Wq : (idx < 32768 ? Wk : Wv);
    const int local = (idx & 16383) * 4;
    float4 w = *(const float4*)&W[local];
    float4 h, l;
    h.x = tf32r(w.x); l.x = tf32r(w.x - h.x);
    h.y = tf32r(w.y); l.y = tf32r(w.y - h.y);
    h.z = tf32r(w.z); l.z = tf32r(w.z - h.z);
    h.w = tf32r(w.w); l.w = tf32r(w.w - h.w);
    *(float4*)&g_wh[idx * 4] = h;
    *(float4*)&g_wl[idx * 4] = l;
}

// ---------------------------------------------------------------------------
// Kernel 1: QKV projection, 2-term TF32 mma (X truncated, W exact via hi+lo):
//   acc += tf32(X)*Wh + tf32(X)*Wl.   256 threads (8 warps).
// ---------------------------------------------------------------------------
#define QBM 128
#define QBK 16
#define A_STR 20
#define B_STR 72
#define NKITER (CDIM / QBK)   // 64

__global__ __launch_bounds__(256) void qkv_tc(
    const float* __restrict__ xq, const float* __restrict__ xkv)
{
    const int which = blockIdx.y;                 // 0=Q, 1=K, 2=V
    const float* __restrict__ X  = (which == 0) ? xq : xkv;
    const float* __restrict__ WH = g_wh + which * CDIM * HS;
    const float* __restrict__ WL = g_wl + which * CDIM * HS;
    float* __restrict__ O = (which == 0) ? g_q : (which == 1 ? g_k : g_v);

    __shared__ __align__(16) float As[2][QBM][A_STR];
    __shared__ __align__(16) float Bh[2][QBK][B_STR];
    __shared__ __align__(16) float Bl[2][QBK][B_STR];

    const int tid  = threadIdx.x;
    const int warp = tid >> 5;
    const int lane = tid & 31;
    const int m0   = blockIdx.x * QBM;

    float4 acc[8];
#pragma unroll
    for (int nt = 0; nt < 8; nt++) acc[nt] = make_float4(0.f, 0.f, 0.f, 0.f);

    auto load_tile = [&](int it, int buf) {
        const int k0 = it * QBK;
#pragma unroll
        for (int i = 0; i < 2; i++) {
            int idx = tid + i * 256;       // 0..511
            int r   = idx >> 2;
            int c4  = (idx & 3) * 4;
            cpa16(&As[buf][r][c4], &X[(size_t)(m0 + r) * CDIM + k0 + c4]);
        }
        {
            int r  = tid >> 4;             // 0..15
            int c4 = (tid & 15) * 4;
            cpa16(&Bh[buf][r][c4], &WH[(size_t)(k0 + r) * HS + c4]);
            cpa16(&Bl[buf][r][c4], &WL[(size_t)(k0 + r) * HS + c4]);
        }
    };

    load_tile(0, 0);
    CP_COMMIT();

    const int arow = warp * 16 + (lane >> 2);
    const int kq   = lane & 3;
    const int bcol = lane >> 2;

    for (int it = 0; it < NKITER; it++) {
        const int buf = it & 1;
        if (it + 1 < NKITER) {
            load_tile(it + 1, buf ^ 1);
            CP_COMMIT();
            CP_WAIT(1);
        } else {
            CP_WAIT(0);
        }
        __syncthreads();

#pragma unroll
        for (int kk = 0; kk < 2; kk++) {
            const int ks = kk * 8;
            float ah[4];
            ah[0] = tf32r(As[buf][arow][ks + kq]);
            ah[1] = tf32r(As[buf][arow + 8][ks + kq]);
            ah[2] = tf32r(As[buf][arow][ks + kq + 4]);
            ah[3] = tf32r(As[buf][arow + 8][ks + kq + 4]);
#pragma unroll
            for (int nt = 0; nt < 8; nt++) {
                float bh[2], bl[2];
                bh[0] = Bh[buf][ks + kq][nt * 8 + bcol];
                bh[1] = Bh[buf][ks + kq + 4][nt * 8 + bcol];
                bl[0] = Bl[buf][ks + kq][nt * 8 + bcol];
                bl[1] = Bl[buf][ks + kq + 4][nt * 8 + bcol];
                mma_tf32(acc[nt], ah, bh);
                mma_tf32(acc[nt], ah, bl);
            }
        }
        __syncthreads();
    }

    {
        const int row0 = m0 + warp * 16 + (lane >> 2);
#pragma unroll
        for (int nt = 0; nt < 8; nt++) {
            const int col = nt * 8 + 2 * (lane & 3);
            *(float2*)&O[(size_t)row0 * HS + col] =
                make_float2(acc[nt].x, acc[nt].y);
            *(float2*)&O[(size_t)(row0 + 8) * HS + col] =
                make_float2(acc[nt].z, acc[nt].w);
        }
    }
}

// ---------------------------------------------------------------------------
// Kernel 2: split-KV causal flash attention.
// S = QK^T single-pass tf32; PV = (Ph + Pl) x tf32(V) (2 mmas, V single-pass).
// smem 2 buffers (KVh + Ps) = 34.8 KB -> ~5-6 CTAs/SM.
// grid = (NQT, NCHUNK, BATCH), block = 128 (4 warps).
// ---------------------------------------------------------------------------
#define AST 68

__global__ __launch_bounds__(128) void attn_tc(void)
{
    extern __shared__ float sm[];
    float* KVh = sm;                    // [64][AST]  (K hi, then V hi)
    float* Ps  = sm + 64 * AST;         // [64][AST]

    const int qt  = blockIdx.x;
    const int cix = blockIdx.y;
    const int bb  = blockIdx.z;
    if (cix * 4 > qt) return;

    const int tid  = threadIdx.x;
    const int warp = tid >> 5;
    const int lane = tid & 31;
    const int r    = lane >> 2;        // 0..7 (fragment row / B col)
    const int kq   = lane & 3;         // quad k
    const float scale = 0.03125f;      // 1024^-0.5

    // ---- Q fragments hoisted (single tf32; no lo part needed)
    float qh[8][4];
    {
        const float* Qg = g_q + ((size_t)bb * SEQ + qt * 64 + warp * 16) * HS;
#pragma unroll
        for (int ks = 0; ks < 8; ks++) {
            qh[ks][0] = tf32r(Qg[r * HS + 8 * ks + kq]);
            qh[ks][1] = tf32r(Qg[(r + 8) * HS + 8 * ks + kq]);
            qh[ks][2] = tf32r(Qg[r * HS + 8 * ks + kq + 4]);
            qh[ks][3] = tf32r(Qg[(r + 8) * HS + 8 * ks + kq + 4]);
        }
    }

    float4 o[8];
#pragma unroll
    for (int nt = 0; nt < 8; nt++) o[nt] = make_float4(0.f, 0.f, 0.f, 0.f);
    float m_lo = -INFINITY, m_hi = -INFINITY, l_lo = 0.f, l_hi = 0.f;

    const int kt_begin = cix * 4;
    const int kt_end   = (cix * 4 + 3 < qt) ? (cix * 4 + 3) : qt;

    for (int kt = kt_begin; kt <= kt_end; kt++) {
        const float* Kg = g_k + ((size_t)bb * SEQ + kt * 64) * HS;
        const float* Vg = g_v + ((size_t)bb * SEQ + kt * 64) * HS;

        __syncthreads();   // prev-iter V reads (PV) done before K overwrite

        // ---- K load (tf32 hi only), permuted: h -> (h&~7)|((h&3)<<1)|((h>>2)&1)
#pragma unroll
        for (int i = 0; i < 8; i++) {
            int idx = tid + i * 128;   // float4 id 0..1023
            int row = idx >> 4;
            int c4  = (idx & 15) * 4;
            float4 v = *(const float4*)&Kg[row * HS + c4];
            float vals[4] = {v.x, v.y, v.z, v.w};
#pragma unroll
            for (int j = 0; j < 4; j++) {
                int h = c4 + j;
                int p = (h & ~7) | ((h & 3) << 1) | ((h >> 2) & 1);
                KVh[row * AST + p] = tf32r(vals[j]);
            }
        }
        __syncthreads();

        // ---- S = Q K^T (single pass)
        float4 s[8];
#pragma unroll
        for (int nt = 0; nt < 8; nt++) s[nt] = make_float4(0.f, 0.f, 0.f, 0.f);

#pragma unroll
        for (int ks = 0; ks < 8; ks++) {
#pragma unroll
            for (int nt = 0; nt < 8; nt++) {
                const int jrow = nt * 8 + r;
                float2 bh = *(const float2*)&KVh[jrow * AST + 8 * ks + 2 * kq];
                mma_tf32(s[nt], qh[ks], (const float*)&bh);
            }
        }

        // ---- scale + causal mask
        const bool diag = (kt == qt);
        const int irow_lo = warp * 16 + r;
        const int irow_hi = irow_lo + 8;
#pragma unroll
        for (int nt = 0; nt < 8; nt++) {
            const int c0 = nt * 8 + 2 * kq;
            s[nt].x *= scale; s[nt].y *= scale;
            s[nt].z *= scale; s[nt].w *= scale;
            if (diag) {
                if (c0     > irow_lo) s[nt].x = -INFINITY;
                if (c0 + 1 > irow_lo) s[nt].y = -INFINITY;
                if (c0     > irow_hi) s[nt].z = -INFINITY;
                if (c0 + 1 > irow_hi) s[nt].w = -INFINITY;
            }
        }

        // ---- row max (local 16 + shuffle over 4-lane group)
        float rmax_lo = -INFINITY, rmax_hi = -INFINITY;
#pragma unroll
        for (int nt = 0; nt < 8; nt++) {
            rmax_lo = fmaxf(rmax_lo, fmaxf(s[nt].x, s[nt].y));
            rmax_hi = fmaxf(rmax_hi, fmaxf(s[nt].z, s[nt].w));
        }
        rmax_lo = fmaxf(rmax_lo, __shfl_xor_sync(0xffffffffu, rmax_lo, 1));
        rmax_lo = fmaxf(rmax_lo, __shfl_xor_sync(0xffffffffu, rmax_lo, 2));
        rmax_hi = fmaxf(rmax_hi, __shfl_xor_sync(0xffffffffu, rmax_hi, 1));
        rmax_hi = fmaxf(rmax_hi, __shfl_xor_sync(0xffffffffu, rmax_hi, 2));

        float mn_lo = fmaxf(m_lo, rmax_lo);
        float mn_hi = fmaxf(m_hi, rmax_hi);
        float alpha_lo = __expf(m_lo - mn_lo);
        float alpha_hi = __expf(m_hi - mn_hi);
        m_lo = mn_lo; m_hi = mn_hi;

        // ---- p = exp(s - m), write raw P to smem, row sums
        float rsum_lo = 0.f, rsum_hi = 0.f;
#pragma unroll
        for (int nt = 0; nt < 8; nt++) {
            const int c0 = nt * 8 + 2 * kq;
            float px = __expf(s[nt].x - m_lo);
            float py = __expf(s[nt].y - m_lo);
            float pz = __expf(s[nt].z - m_hi);
            float pw = __expf(s[nt].w - m_hi);
            rsum_lo += px + py;
            rsum_hi += pz + pw;
            *(float2*)&Ps[irow_lo * AST + c0] = make_float2(px, py);
            *(float2*)&Ps[irow_hi * AST + c0] = make_float2(pz, pw);
        }
        rsum_lo += __shfl_xor_sync(0xffffffffu, rsum_lo, 1);
        rsum_lo += __shfl_xor_sync(0xffffffffu, rsum_lo, 2);
        rsum_hi += __shfl_xor_sync(0xffffffffu, rsum_hi, 1);
        rsum_hi += __shfl_xor_sync(0xffffffffu, rsum_hi, 2);

        l_lo = l_lo * alpha_lo + rsum_lo;
        l_hi = l_hi * alpha_hi + rsum_hi;
#pragma unroll
        for (int nt = 0; nt < 8; nt++) {
            o[nt].x *= alpha_lo; o[nt].y *= alpha_lo;
            o[nt].z *= alpha_hi; o[nt].w *= alpha_hi;
        }

        __syncthreads();   // all warps done reading K before V overwrite

        // ---- V load, single-pass tf32 (natural layout [j][col])
#pragma unroll
        for (int i = 0; i < 8; i++) {
            int idx = tid + i * 128;
            int row = idx >> 4;
            int c4  = (idx & 15) * 4;
            float4 v = *(const float4*)&Vg[row * HS + c4];
            float4 h4;
            h4.x = tf32r(v.x);
            h4.y = tf32r(v.y);
            h4.z = tf32r(v.z);
            h4.w = tf32r(v.w);
            *(float4*)&KVh[row * AST + c4] = h4;
        }
        __syncthreads();

        // ---- O += P V (P split hi/lo for exactness, V single-pass: 2 mmas)
#pragma unroll
        for (int ks = 0; ks < 8; ks++) {
            float raw[4];
            raw[0] = Ps[irow_lo * AST + 8 * ks + kq];
            raw[1] = Ps[irow_hi * AST + 8 * ks + kq];
            raw[2] = Ps[irow_lo * AST + 8 * ks + kq + 4];
            raw[3] = Ps[irow_hi * AST + 8 * ks + kq + 4];
            float ah[4], al[4];
#pragma unroll
            for (int i = 0; i < 4; i++) {
                ah[i] = tf32r(raw[i]);
                al[i] = tf32r(raw[i] - ah[i]);
            }
#pragma unroll
            for (int nt = 0; nt < 8; nt++) {
                float bh[2];
                bh[0] = KVh[(8 * ks + kq) * AST + nt * 8 + r];
                bh[1] = KVh[(8 * ks + kq + 4) * AST + nt * 8 + r];
                mma_tf32(o[nt], ah, bh);
                mma_tf32(o[nt], al, bh);
            }
        }
    }

    // ---- store partials (unnormalized) + m, l
    const size_t p = ((size_t)(bb * NQT + qt) * NCHUNK + cix);
    const int irow_lo = warp * 16 + (lane >> 2);
    const int irow_hi = irow_lo + 8;
#pragma unroll
    for (int nt = 0; nt < 8; nt++) {
        const int c0 = nt * 8 + 2 * (lane & 3);
        *(float2*)&g_po[p * 4096 + irow_lo * 64 + c0] = make_float2(o[nt].x, o[nt].y);
        *(float2*)&g_po[p * 4096 + irow_hi * 64 + c0] = make_float2(o[nt].z, o[nt].w);
    }
    if ((lane & 3) == 0) {
        g_pm[p * 64 + irow_lo] = m_lo;
        g_pm[p * 64 + irow_hi] = m_hi;
        g_pl[p * 64 + irow_lo] = l_lo;
        g_pl[p * 64 + irow_hi] = l_hi;
    }
}

// ---------------------------------------------------------------------------
// Kernel 3: combine split-KV partials.
// grid = (NQT, BATCH, 4), block = 128; each CTA handles 16 rows.
// ---------------------------------------------------------------------------
__global__ __launch_bounds__(128) void attn_reduce(float* __restrict__ out)
{
    const int qt = blockIdx.x;
    const int bb = blockIdx.y;
    const int rz = blockIdx.z;             // row group: rows rz*16..+15
    const int nc = qt / 4 + 1;

    __shared__ float w[NCHUNK][16];
    __shared__ float invL[16];

    const int tid = threadIdx.x;
    const size_t pbase = (size_t)(bb * NQT + qt) * NCHUNK;

    if (tid < 16) {
        const int row = rz * 16 + tid;
        float M = -INFINITY;
        for (int c = 0; c < nc; c++)
            M = fmaxf(M, g_pm[(pbase + c) * 64 + row]);
        float L = 0.f;
        for (int c = 0; c < nc; c++) {
            float wi = __expf(g_pm[(pbase + c) * 64 + row] - M);
            w[c][tid] = wi;
            L += wi * g_pl[(pbase + c) * 64 + row];
        }
        invL[tid] = 1.f / L;
    }
    __syncthreads();

#pragma unroll
    for (int i = 0; i < 2; i++) {
        int idx = tid + i * 128;           // 0..255 float4 slots
        int rl  = idx >> 4;                // 0..15
        int c4  = (idx & 15) * 4;
        const int row = rz * 16 + rl;
        float4 acc = make_float4(0.f, 0.f, 0.f, 0.f);
        for (int c = 0; c < nc; c++) {
            float4 v = *(const float4*)&g_po[(pbase + c) * 4096 + row * 64 + c4];
            float wi = w[c][rl];
            acc.x = fmaf(wi, v.x, acc.x);
            acc.y = fmaf(wi, v.y, acc.y);
            acc.z = fmaf(wi, v.z, acc.z);
            acc.w = fmaf(wi, v.w, acc.w);
        }
        float inv = invL[rl];
        acc.x *= inv; acc.y *= inv; acc.z *= inv; acc.w *= inv;
        *(float4*)&out[((size_t)bb * SEQ + qt * 64 + row) * HS + c4] = acc;
    }
}

// ---------------------------------------------------------------------------
extern "C" void kernel_launch(void* const* d_in, const int* in_sizes, int n_in,
                              void* d_out, int out_size)
{
    const float* xq  = (const float*)d_in[0];
    const float* xkv = (const float*)d_in[1];
    const float* Wq  = (const float*)d_in[2];
    const float* Wk  = (const float*)d_in[3];
    const float* Wv  = (const float*)d_in[4];
    float* out = (float*)d_out;

    const int attn_smem = 2 * 64 * AST * sizeof(float);   // 34816 B
    cudaFuncSetAttribute(attn_tc, cudaFuncAttributeMaxDynamicSharedMemorySize,
                         attn_smem);

    wsplit<<<192, 256>>>(Wq, Wk, Wv);
    qkv_tc<<<dim3(M_TOTAL / QBM, 3), 256>>>(xq, xkv);
    attn_tc<<<dim3(NQT, NCHUNK, BATCH), 128, attn_smem>>>();
    attn_reduce<<<dim3(NQT, BATCH, 4), 128>>>(out);
}

// round 13
// speedup vs baseline: 3.7265x; 1.0074x over previous
#include <cuda_runtime.h>
#include <math.h>
#include <stdint.h>

#define BATCH 8
#define SEQ   2048
#define CDIM  1024
#define HS    64
#define M_TOTAL (BATCH * SEQ)   // 16384

#define NQT    (SEQ / 64)       // 32 query tiles per batch
#define NCHUNK 8                // 8 KV chunks of 256 keys (4 tiles of 64)

// Scratch (device globals: allowed).
__device__ float g_q[M_TOTAL * HS];
__device__ float g_k[M_TOTAL * HS];
__device__ float g_v[M_TOTAL * HS];
__device__ float g_po[(size_t)BATCH * NQT * NCHUNK * 64 * 64];
__device__ float g_pm[BATCH * NQT * NCHUNK * 64];
__device__ float g_pl[BATCH * NQT * NCHUNK * 64];
// Pre-split weights (tf32 hi/lo), layout [which][k][n]
__device__ float g_wh[3 * CDIM * HS];
__device__ float g_wl[3 * CDIM * HS];

// ---------------------------------------------------------------------------
// helpers
// ---------------------------------------------------------------------------
__device__ __forceinline__ float tf32r(float x) {
    uint32_t u;
    asm("cvt.rna.tf32.f32 %0, %1;" : "=r"(u) : "f"(x));
    return __uint_as_float(u);
}

__device__ __forceinline__ void mma_tf32(float4& d, const float* a, const float* b) {
    asm volatile(
        "mma.sync.aligned.m16n8k8.row.col.f32.tf32.tf32.f32 "
        "{%0,%1,%2,%3}, {%4,%5,%6,%7}, {%8,%9}, {%0,%1,%2,%3};"
        : "+f"(d.x), "+f"(d.y), "+f"(d.z), "+f"(d.w)
        : "r"(__float_as_uint(a[0])), "r"(__float_as_uint(a[1])),
          "r"(__float_as_uint(a[2])), "r"(__float_as_uint(a[3])),
          "r"(__float_as_uint(b[0])), "r"(__float_as_uint(b[1])));
}

__device__ __forceinline__ void cpa16(void* smem_dst, const void* gmem_src) {
    uint32_t s = (uint32_t)__cvta_generic_to_shared(smem_dst);
    asm volatile("cp.async.cg.shared.global [%0], [%1], 16;" :: "r"(s), "l"(gmem_src));
}
#define CP_COMMIT() asm volatile("cp.async.commit_group;")
#define CP_WAIT(n)  asm volatile("cp.async.wait_group %0;" :: "n"(n))

// ---------------------------------------------------------------------------
// Kernel 0: split W into tf32 hi/lo. 3*1024*64 = 196608 floats = 49152 float4.
// ---------------------------------------------------------------------------
__global__ __launch_bounds__(256) void wsplit(
    const float* __restrict__ Wq, const float* __restrict__ Wk,
    const float* __restrict__ Wv)
{
    const int idx = blockIdx.x * 256 + threadIdx.x;      // float4 id, 0..49151
    const float* W = (idx < 16384) ? Wq : (idx < 32768 ? Wk : Wv);
    const int local = (idx & 16383) * 4;
    float4 w = *(const float4*)&W[local];
    float4 h, l;
    h.x = tf32r(w.x); l.x = tf32r(w.x - h.x);
    h.y = tf32r(w.y); l.y = tf32r(w.y - h.y);
    h.z = tf32r(w.z); l.z = tf32r(w.z - h.z);
    h.w = tf32r(w.w); l.w = tf32r(w.w - h.w);
    *(float4*)&g_wh[idx * 4] = h;
    *(float4*)&g_wl[idx * 4] = l;
}

// ---------------------------------------------------------------------------
// Kernel 1: QKV projection, 2-term TF32 mma (X truncated, W exact via hi+lo):
//   acc += tf32(X)*Wh + tf32(X)*Wl.   256 threads (8 warps).
// ---------------------------------------------------------------------------
#define QBM 128
#define QBK 16
#define A_STR 20
#define B_STR 72
#define NKITER (CDIM / QBK)   // 64

__global__ __launch_bounds__(256) void qkv_tc(
    const float* __restrict__ xq, const float* __restrict__ xkv)
{
    const int which = blockIdx.y;                 // 0=Q, 1=K, 2=V
    const float* __restrict__ X  = (which == 0) ? xq : xkv;
    const float* __restrict__ WH = g_wh + which * CDIM * HS;
    const float* __restrict__ WL = g_wl + which * CDIM * HS;
    float* __restrict__ O = (which == 0) ? g_q : (which == 1 ? g_k : g_v);

    __shared__ __align__(16) float As[2][QBM][A_STR];
    __shared__ __align__(16) float Bh[2][QBK][B_STR];
    __shared__ __align__(16) float Bl[2][QBK][B_STR];

    const int tid  = threadIdx.x;
    const int warp = tid >> 5;
    const int lane = tid & 31;
    const int m0   = blockIdx.x * QBM;

    float4 acc[8];
#pragma unroll
    for (int nt = 0; nt < 8; nt++) acc[nt] = make_float4(0.f, 0.f, 0.f, 0.f);

    auto load_tile = [&](int it, int buf) {
        const int k0 = it * QBK;
#pragma unroll
        for (int i = 0; i < 2; i++) {
            int idx = tid + i * 256;       // 0..511
            int r   = idx >> 2;
            int c4  = (idx & 3) * 4;
            cpa16(&As[buf][r][c4], &X[(size_t)(m0 + r) * CDIM + k0 + c4]);
        }
        {
            int r  = tid >> 4;             // 0..15
            int c4 = (tid & 15) * 4;
            cpa16(&Bh[buf][r][c4], &WH[(size_t)(k0 + r) * HS + c4]);
            cpa16(&Bl[buf][r][c4], &WL[(size_t)(k0 + r) * HS + c4]);
        }
    };

    load_tile(0, 0);
    CP_COMMIT();

    const int arow = warp * 16 + (lane >> 2);
    const int kq   = lane & 3;
    const int bcol = lane >> 2;

    for (int it = 0; it < NKITER; it++) {
        const int buf = it & 1;
        if (it + 1 < NKITER) {
            load_tile(it + 1, buf ^ 1);
            CP_COMMIT();
            CP_WAIT(1);
        } else {
            CP_WAIT(0);
        }
        __syncthreads();

#pragma unroll
        for (int kk = 0; kk < 2; kk++) {
            const int ks = kk * 8;
            float ah[4];
            ah[0] = tf32r(As[buf][arow][ks + kq]);
            ah[1] = tf32r(As[buf][arow + 8][ks + kq]);
            ah[2] = tf32r(As[buf][arow][ks + kq + 4]);
            ah[3] = tf32r(As[buf][arow + 8][ks + kq + 4]);
#pragma unroll
            for (int nt = 0; nt < 8; nt++) {
                float bh[2], bl[2];
                bh[0] = Bh[buf][ks + kq][nt * 8 + bcol];
                bh[1] = Bh[buf][ks + kq + 4][nt * 8 + bcol];
                bl[0] = Bl[buf][ks + kq][nt * 8 + bcol];
                bl[1] = Bl[buf][ks + kq + 4][nt * 8 + bcol];
                mma_tf32(acc[nt], ah, bh);
                mma_tf32(acc[nt], ah, bl);
            }
        }
        __syncthreads();
    }

    {
        const int row0 = m0 + warp * 16 + (lane >> 2);
#pragma unroll
        for (int nt = 0; nt < 8; nt++) {
            const int col = nt * 8 + 2 * (lane & 3);
            *(float2*)&O[(size_t)row0 * HS + col] =
                make_float2(acc[nt].x, acc[nt].y);
            *(float2*)&O[(size_t)(row0 + 8) * HS + col] =
                make_float2(acc[nt].z, acc[nt].w);
        }
    }
}

// ---------------------------------------------------------------------------
// Kernel 2: split-KV causal flash attention.
// S = QK^T single-pass tf32; PV = tf32(P) x tf32(V) single-pass (1 mma).
// smem 2 buffers (KVh + Ps) = 34.8 KB -> ~5-6 CTAs/SM.
// grid = (NQT, NCHUNK, BATCH), block = 128 (4 warps).
// ---------------------------------------------------------------------------
#define AST 68

__global__ __launch_bounds__(128) void attn_tc(void)
{
    extern __shared__ float sm[];
    float* KVh = sm;                    // [64][AST]  (K hi, then V hi)
    float* Ps  = sm + 64 * AST;         // [64][AST]

    const int qt  = blockIdx.x;
    const int cix = blockIdx.y;
    const int bb  = blockIdx.z;
    if (cix * 4 > qt) return;

    const int tid  = threadIdx.x;
    const int warp = tid >> 5;
    const int lane = tid & 31;
    const int r    = lane >> 2;        // 0..7 (fragment row / B col)
    const int kq   = lane & 3;         // quad k
    const float scale = 0.03125f;      // 1024^-0.5

    // ---- Q fragments hoisted (single tf32; no lo part needed)
    float qh[8][4];
    {
        const float* Qg = g_q + ((size_t)bb * SEQ + qt * 64 + warp * 16) * HS;
#pragma unroll
        for (int ks = 0; ks < 8; ks++) {
            qh[ks][0] = tf32r(Qg[r * HS + 8 * ks + kq]);
            qh[ks][1] = tf32r(Qg[(r + 8) * HS + 8 * ks + kq]);
            qh[ks][2] = tf32r(Qg[r * HS + 8 * ks + kq + 4]);
            qh[ks][3] = tf32r(Qg[(r + 8) * HS + 8 * ks + kq + 4]);
        }
    }

    float4 o[8];
#pragma unroll
    for (int nt = 0; nt < 8; nt++) o[nt] = make_float4(0.f, 0.f, 0.f, 0.f);
    float m_lo = -INFINITY, m_hi = -INFINITY, l_lo = 0.f, l_hi = 0.f;

    const int kt_begin = cix * 4;
    const int kt_end   = (cix * 4 + 3 < qt) ? (cix * 4 + 3) : qt;

    for (int kt = kt_begin; kt <= kt_end; kt++) {
        const float* Kg = g_k + ((size_t)bb * SEQ + kt * 64) * HS;
        const float* Vg = g_v + ((size_t)bb * SEQ + kt * 64) * HS;

        __syncthreads();   // prev-iter V reads (PV) done before K overwrite

        // ---- K load (tf32 hi only), permuted: h -> (h&~7)|((h&3)<<1)|((h>>2)&1)
#pragma unroll
        for (int i = 0; i < 8; i++) {
            int idx = tid + i * 128;   // float4 id 0..1023
            int row = idx >> 4;
            int c4  = (idx & 15) * 4;
            float4 v = *(const float4*)&Kg[row * HS + c4];
            float vals[4] = {v.x, v.y, v.z, v.w};
#pragma unroll
            for (int j = 0; j < 4; j++) {
                int h = c4 + j;
                int p = (h & ~7) | ((h & 3) << 1) | ((h >> 2) & 1);
                KVh[row * AST + p] = tf32r(vals[j]);
            }
        }
        __syncthreads();

        // ---- S = Q K^T (single pass)
        float4 s[8];
#pragma unroll
        for (int nt = 0; nt < 8; nt++) s[nt] = make_float4(0.f, 0.f, 0.f, 0.f);

#pragma unroll
        for (int ks = 0; ks < 8; ks++) {
#pragma unroll
            for (int nt = 0; nt < 8; nt++) {
                const int jrow = nt * 8 + r;
                float2 bh = *(const float2*)&KVh[jrow * AST + 8 * ks + 2 * kq];
                mma_tf32(s[nt], qh[ks], (const float*)&bh);
            }
        }

        // ---- scale + causal mask
        const bool diag = (kt == qt);
        const int irow_lo = warp * 16 + r;
        const int irow_hi = irow_lo + 8;
#pragma unroll
        for (int nt = 0; nt < 8; nt++) {
            const int c0 = nt * 8 + 2 * kq;
            s[nt].x *= scale; s[nt].y *= scale;
            s[nt].z *= scale; s[nt].w *= scale;
            if (diag) {
                if (c0     > irow_lo) s[nt].x = -INFINITY;
                if (c0 + 1 > irow_lo) s[nt].y = -INFINITY;
                if (c0     > irow_hi) s[nt].z = -INFINITY;
                if (c0 + 1 > irow_hi) s[nt].w = -INFINITY;
            }
        }

        // ---- row max (local 16 + shuffle over 4-lane group)
        float rmax_lo = -INFINITY, rmax_hi = -INFINITY;
#pragma unroll
        for (int nt = 0; nt < 8; nt++) {
            rmax_lo = fmaxf(rmax_lo, fmaxf(s[nt].x, s[nt].y));
            rmax_hi = fmaxf(rmax_hi, fmaxf(s[nt].z, s[nt].w));
        }
        rmax_lo = fmaxf(rmax_lo, __shfl_xor_sync(0xffffffffu, rmax_lo, 1));
        rmax_lo = fmaxf(rmax_lo, __shfl_xor_sync(0xffffffffu, rmax_lo, 2));
        rmax_hi = fmaxf(rmax_hi, __shfl_xor_sync(0xffffffffu, rmax_hi, 1));
        rmax_hi = fmaxf(rmax_hi, __shfl_xor_sync(0xffffffffu, rmax_hi, 2));

        float mn_lo = fmaxf(m_lo, rmax_lo);
        float mn_hi = fmaxf(m_hi, rmax_hi);
        float alpha_lo = __expf(m_lo - mn_lo);
        float alpha_hi = __expf(m_hi - mn_hi);
        m_lo = mn_lo; m_hi = mn_hi;

        // ---- p = exp(s - m), write tf32(P) to smem, row sums (fp32 exact)
        float rsum_lo = 0.f, rsum_hi = 0.f;
#pragma unroll
        for (int nt = 0; nt < 8; nt++) {
            const int c0 = nt * 8 + 2 * kq;
            float px = __expf(s[nt].x - m_lo);
            float py = __expf(s[nt].y - m_lo);
            float pz = __expf(s[nt].z - m_hi);
            float pw = __expf(s[nt].w - m_hi);
            rsum_lo += px + py;
            rsum_hi += pz + pw;
            *(float2*)&Ps[irow_lo * AST + c0] = make_float2(tf32r(px), tf32r(py));
            *(float2*)&Ps[irow_hi * AST + c0] = make_float2(tf32r(pz), tf32r(pw));
        }
        rsum_lo += __shfl_xor_sync(0xffffffffu, rsum_lo, 1);
        rsum_lo += __shfl_xor_sync(0xffffffffu, rsum_lo, 2);
        rsum_hi += __shfl_xor_sync(0xffffffffu, rsum_hi, 1);
        rsum_hi += __shfl_xor_sync(0xffffffffu, rsum_hi, 2);

        l_lo = l_lo * alpha_lo + rsum_lo;
        l_hi = l_hi * alpha_hi + rsum_hi;
#pragma unroll
        for (int nt = 0; nt < 8; nt++) {
            o[nt].x *= alpha_lo; o[nt].y *= alpha_lo;
            o[nt].z *= alpha_hi; o[nt].w *= alpha_hi;
        }

        __syncthreads();   // all warps done reading K before V overwrite

        // ---- V load, single-pass tf32 (natural layout [j][col])
#pragma unroll
        for (int i = 0; i < 8; i++) {
            int idx = tid + i * 128;
            int row = idx >> 4;
            int c4  = (idx & 15) * 4;
            float4 v = *(const float4*)&Vg[row * HS + c4];
            float4 h4;
            h4.x = tf32r(v.x);
            h4.y = tf32r(v.y);
            h4.z = tf32r(v.z);
            h4.w = tf32r(v.w);
            *(float4*)&KVh[row * AST + c4] = h4;
        }
        __syncthreads();

        // ---- O += P V (both single-pass tf32: 1 mma)
#pragma unroll
        for (int ks = 0; ks < 8; ks++) {
            float ah[4];
            ah[0] = Ps[irow_lo * AST + 8 * ks + kq];
            ah[1] = Ps[irow_hi * AST + 8 * ks + kq];
            ah[2] = Ps[irow_lo * AST + 8 * ks + kq + 4];
            ah[3] = Ps[irow_hi * AST + 8 * ks + kq + 4];
#pragma unroll
            for (int nt = 0; nt < 8; nt++) {
                float bh[2];
                bh[0] = KVh[(8 * ks + kq) * AST + nt * 8 + r];
                bh[1] = KVh[(8 * ks + kq + 4) * AST + nt * 8 + r];
                mma_tf32(o[nt], ah, bh);
            }
        }
    }

    // ---- store partials (unnormalized) + m, l
    const size_t p = ((size_t)(bb * NQT + qt) * NCHUNK + cix);
    const int irow_lo = warp * 16 + (lane >> 2);
    const int irow_hi = irow_lo + 8;
#pragma unroll
    for (int nt = 0; nt < 8; nt++) {
        const int c0 = nt * 8 + 2 * (lane & 3);
        *(float2*)&g_po[p * 4096 + irow_lo * 64 + c0] = make_float2(o[nt].x, o[nt].y);
        *(float2*)&g_po[p * 4096 + irow_hi * 64 + c0] = make_float2(o[nt].z, o[nt].w);
    }
    if ((lane & 3) == 0) {
        g_pm[p * 64 + irow_lo] = m_lo;
        g_pm[p * 64 + irow_hi] = m_hi;
        g_pl[p * 64 + irow_lo] = l_lo;
        g_pl[p * 64 + irow_hi] = l_hi;
    }
}

// ---------------------------------------------------------------------------
// Kernel 3: combine split-KV partials.
// grid = (NQT, BATCH, 4), block = 128; each CTA handles 16 rows.
// ---------------------------------------------------------------------------
__global__ __launch_bounds__(128) void attn_reduce(float* __restrict__ out)
{
    const int qt = blockIdx.x;
    const int bb = blockIdx.y;
    const int rz = blockIdx.z;             // row group: rows rz*16..+15
    const int nc = qt / 4 + 1;

    __shared__ float w[NCHUNK][16];
    __shared__ float invL[16];

    const int tid = threadIdx.x;
    const size_t pbase = (size_t)(bb * NQT + qt) * NCHUNK;

    if (tid < 16) {
        const int row = rz * 16 + tid;
        float M = -INFINITY;
        for (int c = 0; c < nc; c++)
            M = fmaxf(M, g_pm[(pbase + c) * 64 + row]);
        float L = 0.f;
        for (int c = 0; c < nc; c++) {
            float wi = __expf(g_pm[(pbase + c) * 64 + row] - M);
            w[c][tid] = wi;
            L += wi * g_pl[(pbase + c) * 64 + row];
        }
        invL[tid] = 1.f / L;
    }
    __syncthreads();

#pragma unroll
    for (int i = 0; i < 2; i++) {
        int idx = tid + i * 128;           // 0..255 float4 slots
        int rl  = idx >> 4;                // 0..15
        int c4  = (idx & 15) * 4;
        const int row = rz * 16 + rl;
        float4 acc = make_float4(0.f, 0.f, 0.f, 0.f);
        for (int c = 0; c < nc; c++) {
            float4 v = *(const float4*)&g_po[(pbase + c) * 4096 + row * 64 + c4];
            float wi = w[c][rl];
            acc.x = fmaf(wi, v.x, acc.x);
            acc.y = fmaf(wi, v.y, acc.y);
            acc.z = fmaf(wi, v.z, acc.z);
            acc.w = fmaf(wi, v.w, acc.w);
        }
        float inv = invL[rl];
        acc.x *= inv; acc.y *= inv; acc.z *= inv; acc.w *= inv;
        *(float4*)&out[((size_t)bb * SEQ + qt * 64 + row) * HS + c4] = acc;
    }
}

// ---------------------------------------------------------------------------
extern "C" void kernel_launch(void* const* d_in, const int* in_sizes, int n_in,
                              void* d_out, int out_size)
{
    const float* xq  = (const float*)d_in[0];
    const float* xkv = (const float*)d_in[1];
    const float* Wq  = (const float*)d_in[2];
    const float* Wk  = (const float*)d_in[3];
    const float* Wv  = (const float*)d_in[4];
    float* out = (float*)d_out;

    const int attn_smem = 2 * 64 * AST * sizeof(float);   // 34816 B
    cudaFuncSetAttribute(attn_tc, cudaFuncAttributeMaxDynamicSharedMemorySize,
                         attn_smem);

    wsplit<<<192, 256>>>(Wq, Wk, Wv);
    qkv_tc<<<dim3(M_TOTAL / QBM, 3), 256>>>(xq, xkv);
    attn_tc<<<dim3(NQT, NCHUNK, BATCH), 128, attn_smem>>>();
    attn_reduce<<<dim3(NQT, BATCH, 4), 128>>>(out);
}